// round 4
// baseline (speedup 1.0000x reference)
#include <cuda_runtime.h>

// ----------------------------------------------------------------------------
// MultiHeadedAttention (temporal mask), fp32 baseline.
//   B=256, S=176 (8 time x 22 joints), D_in=128, H=8, Hd=32, D_model=256
//   out[b,s,h*32+d] = softmax_t( mask(q·k)/sqrt(32) ) @ relu(v)
// Kernel 1: fused QKV projection GEMM -> scratch [B,H,S,32] layouts
// Kernel 2: per-(b,h) fused attention (scores + masked softmax + att@V)
// ----------------------------------------------------------------------------

#define BQ      256
#define SEQ     176
#define DIN     128
#define DMODEL  256
#define HNUM    8
#define HDIM    32
#define MROWS   (BQ * SEQ)        // 45056 = 704 * 64
#define JOINTS  22

#define KT_STRIDE 193             // 176 data + zero pad to 193 (odd -> conflict-free)
#define SC_STRIDE 180             // 176 rounded to mult-of-4 + spread

// Scratch (allocation-free rule: __device__ globals). 3 x 46 MB.
__device__ __align__(256) float gQ[BQ * HNUM * SEQ * HDIM];
__device__ __align__(256) float gK[BQ * HNUM * SEQ * HDIM];
__device__ __align__(256) float gV[BQ * HNUM * SEQ * HDIM];

// ----------------------------------------------------------------------------
// Kernel 1: QKV projection. grid = (704, 4, 3), block = 256.
// Block computes 64 rows x 64 cols of one of Q/K/V. K=128 in two 64-steps.
// ----------------------------------------------------------------------------
__global__ __launch_bounds__(256) void qkv_kernel(
    const float* __restrict__ x,
    const float* __restrict__ Wq, const float* __restrict__ bq,
    const float* __restrict__ Wk, const float* __restrict__ bk,
    const float* __restrict__ Wv, const float* __restrict__ bv)
{
    const int z = blockIdx.z;
    const float* __restrict__ W    = (z == 0) ? Wq : ((z == 1) ? Wk : Wv);
    const float* __restrict__ bias = (z == 0) ? bq : ((z == 1) ? bk : bv);
    float* __restrict__ out        = (z == 0) ? gQ : ((z == 1) ? gK : gV);
    const bool relu = (z == 2);

    __shared__ float As[64][65];   // [k][row], pad 65: conflict-free broadcast reads
    __shared__ float Bs[64][65];   // [k][col]

    const int tid = threadIdx.x;
    const int tx  = tid & 15;
    const int ty  = tid >> 4;
    const int tx4 = tx << 2;
    const int ty4 = ty << 2;
    const int rm  = blockIdx.x * 64;
    const int cn  = blockIdx.y * 64;

    float acc[4][4];
#pragma unroll
    for (int i = 0; i < 4; i++)
#pragma unroll
        for (int j = 0; j < 4; j++) acc[i][j] = 0.0f;

    for (int k0 = 0; k0 < DIN; k0 += 64) {
        // Load x tile 64x64 (coalesced float4), store transposed [k][row]
#pragma unroll
        for (int q = tid; q < 1024; q += 256) {
            int row = q >> 4;
            int kq  = (q & 15) << 2;
            float4 v = *(const float4*)(x + (size_t)(rm + row) * DIN + k0 + kq);
            As[kq + 0][row] = v.x;
            As[kq + 1][row] = v.y;
            As[kq + 2][row] = v.z;
            As[kq + 3][row] = v.w;
        }
        // Load W tile 64x64 (coalesced float4), natural [k][col]
#pragma unroll
        for (int q = tid; q < 1024; q += 256) {
            int k  = q >> 4;
            int cq = (q & 15) << 2;
            float4 v = *(const float4*)(W + (size_t)(k0 + k) * DMODEL + cn + cq);
            Bs[k][cq + 0] = v.x;
            Bs[k][cq + 1] = v.y;
            Bs[k][cq + 2] = v.z;
            Bs[k][cq + 3] = v.w;
        }
        __syncthreads();

#pragma unroll 16
        for (int k = 0; k < 64; k++) {
            float a0 = As[k][ty4 + 0], a1 = As[k][ty4 + 1];
            float a2 = As[k][ty4 + 2], a3 = As[k][ty4 + 3];
            float b0 = Bs[k][tx4 + 0], b1 = Bs[k][tx4 + 1];
            float b2 = Bs[k][tx4 + 2], b3 = Bs[k][tx4 + 3];
            acc[0][0] = fmaf(a0, b0, acc[0][0]);
            acc[0][1] = fmaf(a0, b1, acc[0][1]);
            acc[0][2] = fmaf(a0, b2, acc[0][2]);
            acc[0][3] = fmaf(a0, b3, acc[0][3]);
            acc[1][0] = fmaf(a1, b0, acc[1][0]);
            acc[1][1] = fmaf(a1, b1, acc[1][1]);
            acc[1][2] = fmaf(a1, b2, acc[1][2]);
            acc[1][3] = fmaf(a1, b3, acc[1][3]);
            acc[2][0] = fmaf(a2, b0, acc[2][0]);
            acc[2][1] = fmaf(a2, b1, acc[2][1]);
            acc[2][2] = fmaf(a2, b2, acc[2][2]);
            acc[2][3] = fmaf(a2, b3, acc[2][3]);
            acc[3][0] = fmaf(a3, b0, acc[3][0]);
            acc[3][1] = fmaf(a3, b1, acc[3][1]);
            acc[3][2] = fmaf(a3, b2, acc[3][2]);
            acc[3][3] = fmaf(a3, b3, acc[3][3]);
        }
        __syncthreads();
    }

    // Epilogue: +bias, optional ReLU, scatter into [B,H,S,32]
    const int c0 = cn + tx4;                 // 4 consecutive cols, same head
    const int h  = c0 >> 5;
    const int d0 = c0 & 31;
    float4 bb = *(const float4*)(bias + c0);
#pragma unroll
    for (int i = 0; i < 4; i++) {
        int r = rm + ty4 + i;
        int b = r / SEQ;
        int s = r - b * SEQ;
        float4 o;
        o.x = acc[i][0] + bb.x;
        o.y = acc[i][1] + bb.y;
        o.z = acc[i][2] + bb.z;
        o.w = acc[i][3] + bb.w;
        if (relu) {
            o.x = fmaxf(o.x, 0.0f);
            o.y = fmaxf(o.y, 0.0f);
            o.z = fmaxf(o.z, 0.0f);
            o.w = fmaxf(o.w, 0.0f);
        }
        *(float4*)(out + ((size_t)(b * HNUM + h) * SEQ + s) * HDIM + d0) = o;
    }
}

// ----------------------------------------------------------------------------
// Kernel 2: attention per (b,h). block = 256 (8 warps x 22 rows each).
// ----------------------------------------------------------------------------
template <int NR>
__device__ __forceinline__ void attn_rows(
    const float* __restrict__ qs,   // [176][32]
    const float* __restrict__ kt,   // [32][193] transposed, zero pad t>=176
    const float* __restrict__ vs,   // [176][32]
    float* __restrict__ scw,        // this warp's att buffer: [4][SC_STRIDE]
    int sg, int lane,
    float* __restrict__ outBase)    // out + b*SEQ*DMODEL + h*HDIM
{
    // ---- scores: acc[i][j] = q[sg+i] . k[lane+32j] ----
    float acc[NR][6];
#pragma unroll
    for (int i = 0; i < NR; i++)
#pragma unroll
        for (int j = 0; j < 6; j++) acc[i][j] = 0.0f;

#pragma unroll
    for (int d4 = 0; d4 < HDIM; d4 += 4) {
        float4 qv[NR];
#pragma unroll
        for (int i = 0; i < NR; i++)
            qv[i] = *(const float4*)(qs + (sg + i) * HDIM + d4);
#pragma unroll
        for (int j = 0; j < 6; j++) {
            int t = lane + 32 * j;
            float k0 = kt[(d4 + 0) * KT_STRIDE + t];
            float k1 = kt[(d4 + 1) * KT_STRIDE + t];
            float k2 = kt[(d4 + 2) * KT_STRIDE + t];
            float k3 = kt[(d4 + 3) * KT_STRIDE + t];
#pragma unroll
            for (int i = 0; i < NR; i++) {
                acc[i][j] = fmaf(qv[i].x, k0, acc[i][j]);
                acc[i][j] = fmaf(qv[i].y, k1, acc[i][j]);
                acc[i][j] = fmaf(qv[i].z, k2, acc[i][j]);
                acc[i][j] = fmaf(qv[i].w, k3, acc[i][j]);
            }
        }
    }

    const float scale = 0.17677669529663687f;   // 1/sqrt(32)

    __syncwarp();   // prior group's att reads done before we overwrite scw

    // ---- masked softmax per row; write att to smem ----
#pragma unroll
    for (int i = 0; i < NR; i++) {
        int s    = sg + i;
        int sblk = s / JOINTS;
        float sv[6];
        bool  ok[6];
        float m = -3.0e38f;
#pragma unroll
        for (int j = 0; j < 6; j++) {
            int t = lane + 32 * j;
            // valid unless (same time-block && t != s); t>=176 invalid
            ok[j] = (t < SEQ) && ((t / JOINTS != sblk) || (t == s));
            sv[j] = acc[i][j] * scale;
            if (ok[j]) m = fmaxf(m, sv[j]);
        }
#pragma unroll
        for (int off = 16; off > 0; off >>= 1)
            m = fmaxf(m, __shfl_xor_sync(0xffffffffu, m, off));
        float e[6];
        float sum = 0.0f;
#pragma unroll
        for (int j = 0; j < 6; j++) {
            e[j] = ok[j] ? __expf(sv[j] - m) : 0.0f;
            sum += e[j];
        }
#pragma unroll
        for (int off = 16; off > 0; off >>= 1)
            sum += __shfl_xor_sync(0xffffffffu, sum, off);
        float inv = 1.0f / sum;
#pragma unroll
        for (int j = 0; j < 6; j++) {
            int t = lane + 32 * j;
            if (t < SEQ) scw[i * SC_STRIDE + t] = e[j] * inv;
        }
    }

    __syncwarp();   // att visible to whole warp

    // ---- out[i][lane] = sum_t att[i][t] * v[t][lane] ----
    float o[NR];
#pragma unroll
    for (int i = 0; i < NR; i++) o[i] = 0.0f;

#pragma unroll 4
    for (int tg = 0; tg < SEQ / 4; tg++) {
        float4 av[NR];
#pragma unroll
        for (int i = 0; i < NR; i++)
            av[i] = *(const float4*)(scw + i * SC_STRIDE + tg * 4);
        float v0 = vs[(tg * 4 + 0) * HDIM + lane];
        float v1 = vs[(tg * 4 + 1) * HDIM + lane];
        float v2 = vs[(tg * 4 + 2) * HDIM + lane];
        float v3 = vs[(tg * 4 + 3) * HDIM + lane];
#pragma unroll
        for (int i = 0; i < NR; i++) {
            o[i] = fmaf(av[i].x, v0, o[i]);
            o[i] = fmaf(av[i].y, v1, o[i]);
            o[i] = fmaf(av[i].z, v2, o[i]);
            o[i] = fmaf(av[i].w, v3, o[i]);
        }
    }

#pragma unroll
    for (int i = 0; i < NR; i++)
        outBase[(size_t)(sg + i) * DMODEL + lane] = o[i];
}

__global__ __launch_bounds__(256) void attn_kernel(float* __restrict__ out)
{
    extern __shared__ float smem[];
    float* qs = smem;                                   // 176*32
    float* kt = qs + SEQ * HDIM;                        // 32*193
    float* vs = kt + HDIM * KT_STRIDE;                  // 176*32
    float* sc = vs + SEQ * HDIM;                        // 8*4*180

    const int bh = blockIdx.x;
    const int b  = bh >> 3;
    const int h  = bh & 7;
    const size_t base = (size_t)bh * SEQ * HDIM;
    const float* __restrict__ Qb = gQ + base;
    const float* __restrict__ Kb = gK + base;
    const float* __restrict__ Vb = gV + base;

    const int tid = threadIdx.x;

    // Stage Q, V (float4 coalesced) and K transposed (conflict-free stride 193)
    for (int q = tid; q < SEQ * HDIM / 4; q += 256) {
        ((float4*)qs)[q] = ((const float4*)Qb)[q];
        ((float4*)vs)[q] = ((const float4*)Vb)[q];
    }
    for (int q = tid; q < SEQ * HDIM; q += 256) {
        int t = q >> 5;
        int d = q & 31;
        kt[d * KT_STRIDE + t] = Kb[q];
    }
    for (int q = tid; q < HDIM * (KT_STRIDE - SEQ); q += 256) {
        int d = q / (KT_STRIDE - SEQ);
        int t = SEQ + q % (KT_STRIDE - SEQ);
        kt[d * KT_STRIDE + t] = 0.0f;                   // tail lanes read zeros
    }
    __syncthreads();

    const int warp = tid >> 5;
    const int lane = tid & 31;
    float* scw = sc + warp * (4 * SC_STRIDE);
    float* outBase = out + (size_t)b * SEQ * DMODEL + h * HDIM;
    const int s0 = warp * 22;                           // 8 warps x 22 rows = 176

    attn_rows<4>(qs, kt, vs, scw, s0 +  0, lane, outBase);
    attn_rows<4>(qs, kt, vs, scw, s0 +  4, lane, outBase);
    attn_rows<4>(qs, kt, vs, scw, s0 +  8, lane, outBase);
    attn_rows<4>(qs, kt, vs, scw, s0 + 12, lane, outBase);
    attn_rows<4>(qs, kt, vs, scw, s0 + 16, lane, outBase);
    attn_rows<2>(qs, kt, vs, scw, s0 + 20, lane, outBase);
}

// ----------------------------------------------------------------------------
extern "C" void kernel_launch(void* const* d_in, const int* in_sizes, int n_in,
                              void* d_out, int out_size)
{
    const float* x  = (const float*)d_in[0];
    const float* Wq = (const float*)d_in[1];
    const float* bq = (const float*)d_in[2];
    const float* Wk = (const float*)d_in[3];
    const float* bk = (const float*)d_in[4];
    const float* Wv = (const float*)d_in[5];
    const float* bv = (const float*)d_in[6];
    float* out = (float*)d_out;

    const int smem_bytes =
        (SEQ * HDIM + HDIM * KT_STRIDE + SEQ * HDIM + 8 * 4 * SC_STRIDE) * 4; // 92800
    cudaFuncSetAttribute(attn_kernel,
                         cudaFuncAttributeMaxDynamicSharedMemorySize, smem_bytes);

    qkv_kernel<<<dim3(MROWS / 64, DMODEL / 64, 3), 256>>>(x, Wq, bq, Wk, bk, Wv, bv);
    attn_kernel<<<BQ * HNUM, 256, smem_bytes>>>(out);
}

// round 11
// speedup vs baseline: 1.2772x; 1.2772x over previous
#include <cuda_runtime.h>
#include <cuda_bf16.h>
#include <cstdint>

// ----------------------------------------------------------------------------
// MultiHeadedAttention (temporal mask).
//   B=256, S=176 (8 time x 22 joints), D_in=128, H=8, Hd=32, D_model=256
// Kernel 1: qkv_mma — mma.sync.m16n8k16 bf16 hi/lo split (3 terms), fp32 accum
//           (tcgen05 is unusable: harness compiles PTX at compute_103, no 'a')
// Kernel 2: attn    — per-(b,h) fp32 attention, 16 warps x 11 rows (NR=6+5)
// ----------------------------------------------------------------------------

#define BQ      256
#define SEQ     176
#define DIN     128
#define DMODEL  256
#define HNUM    8
#define HDIM    32
#define MROWS   (BQ * SEQ)        // 45056 = 352 * 128
#define JOINTS  22

#define KT_STRIDE 193
#define SC_STRIDE 180

// Scratch (__device__ globals; no allocation allowed)
__device__ __align__(256) float gQ[BQ * HNUM * SEQ * HDIM];
__device__ __align__(256) float gK[BQ * HNUM * SEQ * HDIM];
__device__ __align__(256) float gV[BQ * HNUM * SEQ * HDIM];

// ---------------- helpers ----------------
__device__ __forceinline__ uint32_t smem_u32(const void* p) {
    uint32_t a;
    asm("{ .reg .u64 t; cvta.to.shared.u64 t, %1; cvt.u32.u64 %0, t; }" : "=r"(a) : "l"(p));
    return a;
}
__device__ __forceinline__ uint32_t pk2(__nv_bfloat16 a, __nv_bfloat16 b) {
    return (uint32_t)__bfloat16_as_ushort(a) | ((uint32_t)__bfloat16_as_ushort(b) << 16);
}

#define LDSM_X4(r0, r1, r2, r3, addr)                                           \
    asm volatile("ldmatrix.sync.aligned.m8n8.x4.shared.b16 {%0,%1,%2,%3}, [%4];" \
        : "=r"(r0), "=r"(r1), "=r"(r2), "=r"(r3) : "r"(addr))
#define LDSM_X4_T(r0, r1, r2, r3, addr)                                         \
    asm volatile("ldmatrix.sync.aligned.m8n8.x4.trans.shared.b16 {%0,%1,%2,%3}, [%4];" \
        : "=r"(r0), "=r"(r1), "=r"(r2), "=r"(r3) : "r"(addr))

#define MMA_BF16(d, a, b)                                                       \
    asm volatile("mma.sync.aligned.m16n8k16.row.col.f32.bf16.bf16.f32 "         \
        "{%0,%1,%2,%3}, {%4,%5,%6,%7}, {%8,%9}, {%0,%1,%2,%3};"                 \
        : "+f"((d)[0]), "+f"((d)[1]), "+f"((d)[2]), "+f"((d)[3])                \
        : "r"((a)[0]), "r"((a)[1]), "r"((a)[2]), "r"((a)[3]),                   \
          "r"((b)[0]), "r"((b)[1]))

// ----------------------------------------------------------------------------
// Kernel 1: QKV via mma.sync. grid=(352,2,3), block=256 (8 warps, 2x4 grid).
// D[128,128] = (A_hi+A_lo)(B_hi+B_lo) approx by 3 terms, fp32 accumulate.
// A = x tile [128 rows][128 k], B = W tile [128 k][128 n] (native layout).
// smem stride 136 elems (272B = 17*16B, odd) -> conflict-free ldmatrix.
// ----------------------------------------------------------------------------
#define AS 136
#define SZ_TILE (128 * AS * 2)         // 34816 bytes per bf16 image
#define SM_AHI  0
#define SM_ALO  (SM_AHI + SZ_TILE)
#define SM_BHI  (SM_ALO + SZ_TILE)
#define SM_BLO  (SM_BHI + SZ_TILE)
#define SM_QKV  (SM_BLO + SZ_TILE)     // 139264 bytes

__global__ __launch_bounds__(256) void qkv_mma(
    const float* __restrict__ x,
    const float* __restrict__ Wq, const float* __restrict__ bq,
    const float* __restrict__ Wk, const float* __restrict__ bk,
    const float* __restrict__ Wv, const float* __restrict__ bv)
{
    extern __shared__ char smem[];
    const uint32_t sb = smem_u32(smem);
    const int tid  = threadIdx.x;
    const int wid  = tid >> 5;
    const int lane = tid & 31;
    const int wr   = wid >> 2;         // warp row 0..1  (64 output rows each)
    const int wc   = wid & 3;          // warp col 0..3  (32 output cols each)
    const int z    = blockIdx.z;
    const int rm   = blockIdx.x * 128;
    const int cn   = blockIdx.y * 128;

    const float* __restrict__ W    = (z == 0) ? Wq : ((z == 1) ? Wk : Wv);
    const float* __restrict__ bias = (z == 0) ? bq : ((z == 1) ? bk : bv);
    float* __restrict__ outp       = (z == 0) ? gQ : ((z == 1) ? gK : gV);

    // ---- stage A (x) and B (W) as bf16 hi/lo, padded stride 136 ----
#pragma unroll
    for (int i = tid; i < 4096; i += 256) {
        int row = i >> 5;              // 0..127
        int kq  = (i & 31) << 2;       // 0..124 step 4
        // A: x[rm+row][kq..kq+3]
        float4 v = *(const float4*)(x + (size_t)(rm + row) * DIN + kq);
        __nv_bfloat16 h0 = __float2bfloat16(v.x), h1 = __float2bfloat16(v.y);
        __nv_bfloat16 h2 = __float2bfloat16(v.z), h3 = __float2bfloat16(v.w);
        uint2 uh; uh.x = pk2(h0, h1); uh.y = pk2(h2, h3);
        uint2 ul;
        ul.x = pk2(__float2bfloat16(v.x - __bfloat162float(h0)),
                   __float2bfloat16(v.y - __bfloat162float(h1)));
        ul.y = pk2(__float2bfloat16(v.z - __bfloat162float(h2)),
                   __float2bfloat16(v.w - __bfloat162float(h3)));
        uint32_t off = (uint32_t)(row * AS + kq) * 2;
        *(uint2*)(smem + SM_AHI + off) = uh;
        *(uint2*)(smem + SM_ALO + off) = ul;
        // B: W[row(k)][cn+kq..+3]  (k index reuses 'row', n reuses 'kq')
        float4 w = *(const float4*)(W + (size_t)row * DMODEL + cn + kq);
        __nv_bfloat16 g0 = __float2bfloat16(w.x), g1 = __float2bfloat16(w.y);
        __nv_bfloat16 g2 = __float2bfloat16(w.z), g3 = __float2bfloat16(w.w);
        uint2 vh; vh.x = pk2(g0, g1); vh.y = pk2(g2, g3);
        uint2 vl;
        vl.x = pk2(__float2bfloat16(w.x - __bfloat162float(g0)),
                   __float2bfloat16(w.y - __bfloat162float(g1)));
        vl.y = pk2(__float2bfloat16(w.z - __bfloat162float(g2)),
                   __float2bfloat16(w.w - __bfloat162float(g3)));
        *(uint2*)(smem + SM_BHI + off) = vh;
        *(uint2*)(smem + SM_BLO + off) = vl;
    }
    __syncthreads();

    // ---- mainloop: 8 k16 steps, 3 split terms ----
    float acc[4][4][4];                 // [m-tile][n-tile][frag]
#pragma unroll
    for (int mt = 0; mt < 4; mt++)
#pragma unroll
        for (int nt = 0; nt < 4; nt++)
#pragma unroll
            for (int r = 0; r < 4; r++) acc[mt][nt][r] = 0.0f;

    // ldmatrix lane addressing (canonical sm_80 recipes)
    const int l16 = lane & 15;
    const int lhi = lane >> 4;          // 0,1
    // A (row-major, non-trans): &A[m0 + l16][ks*16 + lhi*8]
    const uint32_t aRow = (uint32_t)(wr * 64 + l16);
    // B (row-major [k][n], trans): &B[ks*16 + l16][wc*32 + p*16 + lhi*8]
    const uint32_t bCol = (uint32_t)(wc * 32 + lhi * 8);

#pragma unroll
    for (int ks = 0; ks < 8; ks++) {
        uint32_t ah[4][4], al[4][4];    // [m-tile][frag]
#pragma unroll
        for (int mt = 0; mt < 4; mt++) {
            uint32_t off = ((aRow + mt * 16) * AS + ks * 16 + lhi * 8) * 2;
            LDSM_X4(ah[mt][0], ah[mt][1], ah[mt][2], ah[mt][3], sb + SM_AHI + off);
            LDSM_X4(al[mt][0], al[mt][1], al[mt][2], al[mt][3], sb + SM_ALO + off);
        }
        uint32_t bh[4][2], bl[4][2];    // [n-tile][frag]
#pragma unroll
        for (int p = 0; p < 2; p++) {
            uint32_t off = ((uint32_t)(ks * 16 + l16) * AS + bCol + p * 16) * 2;
            uint32_t r0, r1, r2, r3;
            LDSM_X4_T(r0, r1, r2, r3, sb + SM_BHI + off);
            bh[p * 2][0] = r0; bh[p * 2][1] = r1;
            bh[p * 2 + 1][0] = r2; bh[p * 2 + 1][1] = r3;
            LDSM_X4_T(r0, r1, r2, r3, sb + SM_BLO + off);
            bl[p * 2][0] = r0; bl[p * 2][1] = r1;
            bl[p * 2 + 1][0] = r2; bl[p * 2 + 1][1] = r3;
        }
#pragma unroll
        for (int mt = 0; mt < 4; mt++)
#pragma unroll
            for (int nt = 0; nt < 4; nt++) {
                MMA_BF16(acc[mt][nt], ah[mt], bh[nt]);   // Ahi*Bhi
                MMA_BF16(acc[mt][nt], ah[mt], bl[nt]);   // Ahi*Blo
                MMA_BF16(acc[mt][nt], al[mt], bh[nt]);   // Alo*Bhi
            }
    }

    // ---- epilogue: bias (+ReLU for V), scatter to [B,H,S,32] ----
    const int col0 = cn + wc * 32;      // 32 cols = exactly one head
    const int h    = col0 >> 5;
    const int l4r  = lane >> 2;         // 0..7 row-in-8
    const int l4c  = (lane & 3) << 1;   // 0,2,4,6 col pair
#pragma unroll
    for (int mt = 0; mt < 4; mt++) {
#pragma unroll
        for (int nt = 0; nt < 4; nt++) {
            int d = nt * 8 + l4c;
            float2 bb = *(const float2*)(bias + col0 + d);
            int g0 = rm + wr * 64 + mt * 16 + l4r;
            int b0 = g0 / SEQ, s0 = g0 - b0 * SEQ;
            int g1 = g0 + 8;
            int b1 = g1 / SEQ, s1 = g1 - b1 * SEQ;
            float2 o0, o1;
            o0.x = acc[mt][nt][0] + bb.x; o0.y = acc[mt][nt][1] + bb.y;
            o1.x = acc[mt][nt][2] + bb.x; o1.y = acc[mt][nt][3] + bb.y;
            if (z == 2) {
                o0.x = fmaxf(o0.x, 0.0f); o0.y = fmaxf(o0.y, 0.0f);
                o1.x = fmaxf(o1.x, 0.0f); o1.y = fmaxf(o1.y, 0.0f);
            }
            *(float2*)(outp + (((size_t)(b0 * HNUM + h)) * SEQ + s0) * HDIM + d) = o0;
            *(float2*)(outp + (((size_t)(b1 * HNUM + h)) * SEQ + s1) * HDIM + d) = o1;
        }
    }
}

// ----------------------------------------------------------------------------
// Kernel 2: attention per (b,h). block = 512 (16 warps x 11 rows: NR=6 then 5).
// ----------------------------------------------------------------------------
template <int NR>
__device__ __forceinline__ void attn_rows(
    const float* __restrict__ qs,   // [176][32]
    const float* __restrict__ kt,   // [32][193] transposed, zero pad t>=176
    const float* __restrict__ vs,   // [176][32]
    float* __restrict__ scw,        // this warp's att buffer: [6][SC_STRIDE]
    int sg, int lane,
    float* __restrict__ outBase)
{
    float acc[NR][6];
#pragma unroll
    for (int i = 0; i < NR; i++)
#pragma unroll
        for (int j = 0; j < 6; j++) acc[i][j] = 0.0f;

#pragma unroll
    for (int d4 = 0; d4 < HDIM; d4 += 4) {
        float4 qv[NR];
#pragma unroll
        for (int i = 0; i < NR; i++)
            qv[i] = *(const float4*)(qs + (sg + i) * HDIM + d4);
#pragma unroll
        for (int j = 0; j < 6; j++) {
            int t = lane + 32 * j;
            float k0 = kt[(d4 + 0) * KT_STRIDE + t];
            float k1 = kt[(d4 + 1) * KT_STRIDE + t];
            float k2 = kt[(d4 + 2) * KT_STRIDE + t];
            float k3 = kt[(d4 + 3) * KT_STRIDE + t];
#pragma unroll
            for (int i = 0; i < NR; i++) {
                acc[i][j] = fmaf(qv[i].x, k0, acc[i][j]);
                acc[i][j] = fmaf(qv[i].y, k1, acc[i][j]);
                acc[i][j] = fmaf(qv[i].z, k2, acc[i][j]);
                acc[i][j] = fmaf(qv[i].w, k3, acc[i][j]);
            }
        }
    }

    const float scale = 0.17677669529663687f;   // 1/sqrt(32)
    __syncwarp();

#pragma unroll
    for (int i = 0; i < NR; i++) {
        int s    = sg + i;
        int sblk = s / JOINTS;
        float sv[6];
        bool  ok[6];
        float m = -3.0e38f;
#pragma unroll
        for (int j = 0; j < 6; j++) {
            int t = lane + 32 * j;
            ok[j] = (t < SEQ) && ((t / JOINTS != sblk) || (t == s));
            sv[j] = acc[i][j] * scale;
            if (ok[j]) m = fmaxf(m, sv[j]);
        }
#pragma unroll
        for (int off = 16; off > 0; off >>= 1)
            m = fmaxf(m, __shfl_xor_sync(0xffffffffu, m, off));
        float e[6];
        float sum = 0.0f;
#pragma unroll
        for (int j = 0; j < 6; j++) {
            e[j] = ok[j] ? __expf(sv[j] - m) : 0.0f;
            sum += e[j];
        }
#pragma unroll
        for (int off = 16; off > 0; off >>= 1)
            sum += __shfl_xor_sync(0xffffffffu, sum, off);
        float inv = 1.0f / sum;
#pragma unroll
        for (int j = 0; j < 6; j++) {
            int t = lane + 32 * j;
            if (t < SEQ) scw[i * SC_STRIDE + t] = e[j] * inv;
        }
    }

    __syncwarp();

    float o[NR];
#pragma unroll
    for (int i = 0; i < NR; i++) o[i] = 0.0f;

#pragma unroll 4
    for (int tg = 0; tg < SEQ / 4; tg++) {
        float4 av[NR];
#pragma unroll
        for (int i = 0; i < NR; i++)
            av[i] = *(const float4*)(scw + i * SC_STRIDE + tg * 4);
        float v0 = vs[(tg * 4 + 0) * HDIM + lane];
        float v1 = vs[(tg * 4 + 1) * HDIM + lane];
        float v2 = vs[(tg * 4 + 2) * HDIM + lane];
        float v3 = vs[(tg * 4 + 3) * HDIM + lane];
#pragma unroll
        for (int i = 0; i < NR; i++) {
            o[i] = fmaf(av[i].x, v0, o[i]);
            o[i] = fmaf(av[i].y, v1, o[i]);
            o[i] = fmaf(av[i].z, v2, o[i]);
            o[i] = fmaf(av[i].w, v3, o[i]);
        }
    }

#pragma unroll
    for (int i = 0; i < NR; i++)
        outBase[(size_t)(sg + i) * DMODEL + lane] = o[i];
}

__global__ __launch_bounds__(512) void attn_kernel(float* __restrict__ out)
{
    extern __shared__ float smemf[];
    float* qs = smemf;                                  // 176*32
    float* kt = qs + SEQ * HDIM;                        // 32*193
    float* vs = kt + HDIM * KT_STRIDE;                  // 176*32
    float* sc = vs + SEQ * HDIM;                        // 16*6*180

    const int bh = blockIdx.x;
    const int b  = bh >> 3;
    const int h  = bh & 7;
    const size_t base = (size_t)bh * SEQ * HDIM;
    const float* __restrict__ Qb = gQ + base;
    const float* __restrict__ Kb = gK + base;
    const float* __restrict__ Vb = gV + base;

    const int tid = threadIdx.x;

    for (int q = tid; q < SEQ * HDIM / 4; q += 512) {
        ((float4*)qs)[q] = ((const float4*)Qb)[q];
        ((float4*)vs)[q] = ((const float4*)Vb)[q];
    }
    for (int q = tid; q < SEQ * HDIM; q += 512) {
        int t = q >> 5;
        int d = q & 31;
        kt[d * KT_STRIDE + t] = Kb[q];
    }
    for (int q = tid; q < HDIM * (KT_STRIDE - SEQ); q += 512) {
        int d = q / (KT_STRIDE - SEQ);
        int t = SEQ + q % (KT_STRIDE - SEQ);
        kt[d * KT_STRIDE + t] = 0.0f;
    }
    __syncthreads();

    const int warp = tid >> 5;
    const int lane = tid & 31;
    float* scw = sc + warp * (6 * SC_STRIDE);
    float* outBase = out + (size_t)b * SEQ * DMODEL + h * HDIM;
    const int s0 = warp * 11;                           // 16 warps x 11 rows = 176

    attn_rows<6>(qs, kt, vs, scw, s0,     lane, outBase);
    attn_rows<5>(qs, kt, vs, scw, s0 + 6, lane, outBase);
}

// ----------------------------------------------------------------------------
extern "C" void kernel_launch(void* const* d_in, const int* in_sizes, int n_in,
                              void* d_out, int out_size)
{
    const float* x  = (const float*)d_in[0];
    const float* Wq = (const float*)d_in[1];
    const float* bq = (const float*)d_in[2];
    const float* Wk = (const float*)d_in[3];
    const float* bk = (const float*)d_in[4];
    const float* Wv = (const float*)d_in[5];
    const float* bv = (const float*)d_in[6];
    float* out = (float*)d_out;

    const int attn_smem =
        (SEQ * HDIM + HDIM * KT_STRIDE + SEQ * HDIM + 16 * 6 * SC_STRIDE) * 4; // 138880
    cudaFuncSetAttribute(attn_kernel,
                         cudaFuncAttributeMaxDynamicSharedMemorySize, attn_smem);
    cudaFuncSetAttribute(qkv_mma,
                         cudaFuncAttributeMaxDynamicSharedMemorySize, SM_QKV);

    qkv_mma<<<dim3(MROWS / 128, 2, 3), 256, SM_QKV>>>(x, Wq, bq, Wk, bk, Wv, bv);
    attn_kernel<<<BQ * HNUM, 512, attn_smem>>>(out);
}

// round 12
// speedup vs baseline: 2.2615x; 1.7706x over previous
#include <cuda_runtime.h>
#include <cuda_bf16.h>
#include <cstdint>

// ----------------------------------------------------------------------------
// MultiHeadedAttention (temporal mask).
//   B=256, S=176 (8 time x 22 joints), D_in=128, H=8, Hd=32, D_model=256
// Kernel 1: qkv_mma — mma.sync m16n8k16 bf16 hi/lo split (3 terms)  [validated]
// Kernel 2: attn_mma — per-(b,h) FA-style tensor-core attention:
//           scores via split MMA, in-fragment masked softmax, att@V via split
//           MMA reusing score C-frags as A-frags. 12 warps x m16 tile (S->192).
// ----------------------------------------------------------------------------

#define BQ      256
#define SEQ     176
#define DIN     128
#define DMODEL  256
#define HNUM    8
#define HDIM    32
#define MROWS   (BQ * SEQ)        // 45056 = 352 * 128
#define JOINTS  22

// Scratch (__device__ globals; no allocation allowed)
__device__ __align__(256) float gQ[BQ * HNUM * SEQ * HDIM];
__device__ __align__(256) float gK[BQ * HNUM * SEQ * HDIM];
__device__ __align__(256) float gV[BQ * HNUM * SEQ * HDIM];

// ---------------- helpers ----------------
__device__ __forceinline__ uint32_t smem_u32(const void* p) {
    uint32_t a;
    asm("{ .reg .u64 t; cvta.to.shared.u64 t, %1; cvt.u32.u64 %0, t; }" : "=r"(a) : "l"(p));
    return a;
}
__device__ __forceinline__ uint32_t pk2(__nv_bfloat16 a, __nv_bfloat16 b) {
    return (uint32_t)__bfloat16_as_ushort(a) | ((uint32_t)__bfloat16_as_ushort(b) << 16);
}

#define LDSM_X4(r0, r1, r2, r3, addr)                                           \
    asm volatile("ldmatrix.sync.aligned.m8n8.x4.shared.b16 {%0,%1,%2,%3}, [%4];" \
        : "=r"(r0), "=r"(r1), "=r"(r2), "=r"(r3) : "r"(addr))
#define LDSM_X4_T(r0, r1, r2, r3, addr)                                         \
    asm volatile("ldmatrix.sync.aligned.m8n8.x4.trans.shared.b16 {%0,%1,%2,%3}, [%4];" \
        : "=r"(r0), "=r"(r1), "=r"(r2), "=r"(r3) : "r"(addr))

#define MMA_BF16(d, a, b)                                                       \
    asm volatile("mma.sync.aligned.m16n8k16.row.col.f32.bf16.bf16.f32 "         \
        "{%0,%1,%2,%3}, {%4,%5,%6,%7}, {%8,%9}, {%0,%1,%2,%3};"                 \
        : "+f"((d)[0]), "+f"((d)[1]), "+f"((d)[2]), "+f"((d)[3])                \
        : "r"((a)[0]), "r"((a)[1]), "r"((a)[2]), "r"((a)[3]),                   \
          "r"((b)[0]), "r"((b)[1]))
// 2-reg B fragment from an x4_T load: {r0,r1}=tile n, {r2,r3}=tile n+8
#define MMA_BF16_2(d, a, b0, b1)                                                \
    asm volatile("mma.sync.aligned.m16n8k16.row.col.f32.bf16.bf16.f32 "         \
        "{%0,%1,%2,%3}, {%4,%5,%6,%7}, {%8,%9}, {%0,%1,%2,%3};"                 \
        : "+f"((d)[0]), "+f"((d)[1]), "+f"((d)[2]), "+f"((d)[3])                \
        : "r"((a)[0]), "r"((a)[1]), "r"((a)[2]), "r"((a)[3]),                   \
          "r"(b0), "r"(b1))

// ----------------------------------------------------------------------------
// Kernel 1: QKV via mma.sync (unchanged from validated R11 kernel).
// ----------------------------------------------------------------------------
#define AS 136
#define SZ_TILE (128 * AS * 2)
#define SM_AHI  0
#define SM_ALO  (SM_AHI + SZ_TILE)
#define SM_BHI  (SM_ALO + SZ_TILE)
#define SM_BLO  (SM_BHI + SZ_TILE)
#define SM_QKV  (SM_BLO + SZ_TILE)     // 139264 bytes

__global__ __launch_bounds__(256) void qkv_mma(
    const float* __restrict__ x,
    const float* __restrict__ Wq, const float* __restrict__ bq,
    const float* __restrict__ Wk, const float* __restrict__ bk,
    const float* __restrict__ Wv, const float* __restrict__ bv)
{
    extern __shared__ char smem[];
    const uint32_t sb = smem_u32(smem);
    const int tid  = threadIdx.x;
    const int wid  = tid >> 5;
    const int lane = tid & 31;
    const int wr   = wid >> 2;
    const int wc   = wid & 3;
    const int z    = blockIdx.z;
    const int rm   = blockIdx.x * 128;
    const int cn   = blockIdx.y * 128;

    const float* __restrict__ W    = (z == 0) ? Wq : ((z == 1) ? Wk : Wv);
    const float* __restrict__ bias = (z == 0) ? bq : ((z == 1) ? bk : bv);
    float* __restrict__ outp       = (z == 0) ? gQ : ((z == 1) ? gK : gV);

#pragma unroll
    for (int i = tid; i < 4096; i += 256) {
        int row = i >> 5;
        int kq  = (i & 31) << 2;
        float4 v = *(const float4*)(x + (size_t)(rm + row) * DIN + kq);
        __nv_bfloat16 h0 = __float2bfloat16(v.x), h1 = __float2bfloat16(v.y);
        __nv_bfloat16 h2 = __float2bfloat16(v.z), h3 = __float2bfloat16(v.w);
        uint2 uh; uh.x = pk2(h0, h1); uh.y = pk2(h2, h3);
        uint2 ul;
        ul.x = pk2(__float2bfloat16(v.x - __bfloat162float(h0)),
                   __float2bfloat16(v.y - __bfloat162float(h1)));
        ul.y = pk2(__float2bfloat16(v.z - __bfloat162float(h2)),
                   __float2bfloat16(v.w - __bfloat162float(h3)));
        uint32_t off = (uint32_t)(row * AS + kq) * 2;
        *(uint2*)(smem + SM_AHI + off) = uh;
        *(uint2*)(smem + SM_ALO + off) = ul;
        float4 w = *(const float4*)(W + (size_t)row * DMODEL + cn + kq);
        __nv_bfloat16 g0 = __float2bfloat16(w.x), g1 = __float2bfloat16(w.y);
        __nv_bfloat16 g2 = __float2bfloat16(w.z), g3 = __float2bfloat16(w.w);
        uint2 vh; vh.x = pk2(g0, g1); vh.y = pk2(g2, g3);
        uint2 vl;
        vl.x = pk2(__float2bfloat16(w.x - __bfloat162float(g0)),
                   __float2bfloat16(w.y - __bfloat162float(g1)));
        vl.y = pk2(__float2bfloat16(w.z - __bfloat162float(g2)),
                   __float2bfloat16(w.w - __bfloat162float(g3)));
        *(uint2*)(smem + SM_BHI + off) = vh;
        *(uint2*)(smem + SM_BLO + off) = vl;
    }
    __syncthreads();

    float acc[4][4][4];
#pragma unroll
    for (int mt = 0; mt < 4; mt++)
#pragma unroll
        for (int nt = 0; nt < 4; nt++)
#pragma unroll
            for (int r = 0; r < 4; r++) acc[mt][nt][r] = 0.0f;

    const int l16 = lane & 15;
    const int lhi = lane >> 4;
    const uint32_t aRow = (uint32_t)(wr * 64 + l16);
    const uint32_t bCol = (uint32_t)(wc * 32 + lhi * 8);

#pragma unroll
    for (int ks = 0; ks < 8; ks++) {
        uint32_t ah[4][4], al[4][4];
#pragma unroll
        for (int mt = 0; mt < 4; mt++) {
            uint32_t off = ((aRow + mt * 16) * AS + ks * 16 + lhi * 8) * 2;
            LDSM_X4(ah[mt][0], ah[mt][1], ah[mt][2], ah[mt][3], sb + SM_AHI + off);
            LDSM_X4(al[mt][0], al[mt][1], al[mt][2], al[mt][3], sb + SM_ALO + off);
        }
        uint32_t bh[4][2], bl[4][2];
#pragma unroll
        for (int p = 0; p < 2; p++) {
            uint32_t off = ((uint32_t)(ks * 16 + l16) * AS + bCol + p * 16) * 2;
            uint32_t r0, r1, r2, r3;
            LDSM_X4_T(r0, r1, r2, r3, sb + SM_BHI + off);
            bh[p * 2][0] = r0; bh[p * 2][1] = r1;
            bh[p * 2 + 1][0] = r2; bh[p * 2 + 1][1] = r3;
            LDSM_X4_T(r0, r1, r2, r3, sb + SM_BLO + off);
            bl[p * 2][0] = r0; bl[p * 2][1] = r1;
            bl[p * 2 + 1][0] = r2; bl[p * 2 + 1][1] = r3;
        }
#pragma unroll
        for (int mt = 0; mt < 4; mt++)
#pragma unroll
            for (int nt = 0; nt < 4; nt++) {
                MMA_BF16(acc[mt][nt], ah[mt], bh[nt]);
                MMA_BF16(acc[mt][nt], ah[mt], bl[nt]);
                MMA_BF16(acc[mt][nt], al[mt], bh[nt]);
            }
    }

    const int col0 = cn + wc * 32;
    const int h    = col0 >> 5;
    const int l4r  = lane >> 2;
    const int l4c  = (lane & 3) << 1;
#pragma unroll
    for (int mt = 0; mt < 4; mt++) {
#pragma unroll
        for (int nt = 0; nt < 4; nt++) {
            int d = nt * 8 + l4c;
            float2 bb = *(const float2*)(bias + col0 + d);
            int g0 = rm + wr * 64 + mt * 16 + l4r;
            int b0 = g0 / SEQ, s0 = g0 - b0 * SEQ;
            int g1 = g0 + 8;
            int b1 = g1 / SEQ, s1 = g1 - b1 * SEQ;
            float2 o0, o1;
            o0.x = acc[mt][nt][0] + bb.x; o0.y = acc[mt][nt][1] + bb.y;
            o1.x = acc[mt][nt][2] + bb.x; o1.y = acc[mt][nt][3] + bb.y;
            if (z == 2) {
                o0.x = fmaxf(o0.x, 0.0f); o0.y = fmaxf(o0.y, 0.0f);
                o1.x = fmaxf(o1.x, 0.0f); o1.y = fmaxf(o1.y, 0.0f);
            }
            *(float2*)(outp + (((size_t)(b0 * HNUM + h)) * SEQ + s0) * HDIM + d) = o0;
            *(float2*)(outp + (((size_t)(b1 * HNUM + h)) * SEQ + s1) * HDIM + d) = o1;
        }
    }
}

// ----------------------------------------------------------------------------
// Kernel 2: tensor-core attention. grid=2048, block=384 (12 warps x m16 tile).
// smem (bf16): Q hi/lo [192][40], V hi/lo [176][40], Kt hi/lo [32][184].
// ----------------------------------------------------------------------------
#define QS   40                        // 80B row = 5x16B (odd) -> conflict-free
#define KTS  184                       // 368B row = 23x16B (odd)
#define QH_B 0
#define QL_B (QH_B + 192 * QS * 2)     // 15360
#define VH_B (QL_B + 192 * QS * 2)     // 30720
#define VL_B (VH_B + 176 * QS * 2)     // 44800
#define KH_B (VL_B + 176 * QS * 2)     // 58880
#define KL_B (KH_B + 32 * KTS * 2)     // 70656
#define SM_ATT (KL_B + 32 * KTS * 2)   // 82432 bytes

__global__ __launch_bounds__(384, 1) void attn_mma(float* __restrict__ out)
{
    extern __shared__ char smem[];
    const uint32_t sb = smem_u32(smem);
    const int bh = blockIdx.x;
    const int b  = bh >> 3;
    const int h  = bh & 7;
    const size_t base = (size_t)bh * SEQ * HDIM;
    const float* __restrict__ Qb = gQ + base;
    const float* __restrict__ Kb = gK + base;
    const float* __restrict__ Vb = gV + base;
    const int tid = threadIdx.x;

    // ---- stage Q (rows >=176 zeroed) and V as bf16 hi/lo ----
#pragma unroll 2
    for (int i = tid; i < 192 * 8; i += 384) {
        int row = i >> 3, d4 = (i & 7) << 2;
        float4 v = (row < SEQ) ? *(const float4*)(Qb + row * HDIM + d4)
                               : make_float4(0.f, 0.f, 0.f, 0.f);
        __nv_bfloat16 h0 = __float2bfloat16(v.x), h1 = __float2bfloat16(v.y);
        __nv_bfloat16 h2 = __float2bfloat16(v.z), h3 = __float2bfloat16(v.w);
        uint2 uh; uh.x = pk2(h0, h1); uh.y = pk2(h2, h3);
        uint2 ul;
        ul.x = pk2(__float2bfloat16(v.x - __bfloat162float(h0)),
                   __float2bfloat16(v.y - __bfloat162float(h1)));
        ul.y = pk2(__float2bfloat16(v.z - __bfloat162float(h2)),
                   __float2bfloat16(v.w - __bfloat162float(h3)));
        uint32_t off = (uint32_t)(row * QS + d4) * 2;
        *(uint2*)(smem + QH_B + off) = uh;
        *(uint2*)(smem + QL_B + off) = ul;
    }
#pragma unroll 2
    for (int i = tid; i < 176 * 8; i += 384) {
        int row = i >> 3, d4 = (i & 7) << 2;
        float4 v = *(const float4*)(Vb + row * HDIM + d4);
        __nv_bfloat16 h0 = __float2bfloat16(v.x), h1 = __float2bfloat16(v.y);
        __nv_bfloat16 h2 = __float2bfloat16(v.z), h3 = __float2bfloat16(v.w);
        uint2 uh; uh.x = pk2(h0, h1); uh.y = pk2(h2, h3);
        uint2 ul;
        ul.x = pk2(__float2bfloat16(v.x - __bfloat162float(h0)),
                   __float2bfloat16(v.y - __bfloat162float(h1)));
        ul.y = pk2(__float2bfloat16(v.z - __bfloat162float(h2)),
                   __float2bfloat16(v.w - __bfloat162float(h3)));
        uint32_t off = (uint32_t)(row * QS + d4) * 2;
        *(uint2*)(smem + VH_B + off) = uh;
        *(uint2*)(smem + VL_B + off) = ul;
    }
    // K transposed: Kt[d][t]
#pragma unroll 4
    for (int i = tid; i < 176 * 32; i += 384) {
        int t = i >> 5, d = i & 31;
        float kv = Kb[i];
        __nv_bfloat16 kh = __float2bfloat16(kv);
        __nv_bfloat16 kl = __float2bfloat16(kv - __bfloat162float(kh));
        ((__nv_bfloat16*)(smem + KH_B))[d * KTS + t] = kh;
        ((__nv_bfloat16*)(smem + KL_B))[d * KTS + t] = kl;
    }
    __syncthreads();

    const int warp = tid >> 5, lane = tid & 31;
    const int m0  = warp * 16;
    const int l16 = lane & 15, lhi = lane >> 4;
    const int qr  = lane >> 2, qc = (lane & 3) << 1;

    // ---- scores: sc[22 n8-tiles][4], 3-term split MMA ----
    float sc[22][4];
#pragma unroll
    for (int t = 0; t < 22; t++)
#pragma unroll
        for (int r = 0; r < 4; r++) sc[t][r] = 0.0f;

#pragma unroll
    for (int ks = 0; ks < 2; ks++) {
        uint32_t ah[4], al[4];
        uint32_t aoff = (uint32_t)((m0 + l16) * QS + ks * 16 + lhi * 8) * 2;
        LDSM_X4(ah[0], ah[1], ah[2], ah[3], sb + QH_B + aoff);
        LDSM_X4(al[0], al[1], al[2], al[3], sb + QL_B + aoff);
#pragma unroll
        for (int nt2 = 0; nt2 < 11; nt2++) {
            uint32_t boff = (uint32_t)((ks * 16 + l16) * KTS + nt2 * 16 + lhi * 8) * 2;
            uint32_t kh0, kh1, kh2, kh3, kl0, kl1, kl2, kl3;
            LDSM_X4_T(kh0, kh1, kh2, kh3, sb + KH_B + boff);
            LDSM_X4_T(kl0, kl1, kl2, kl3, sb + KL_B + boff);
            MMA_BF16_2(sc[2 * nt2],     ah, kh0, kh1);
            MMA_BF16_2(sc[2 * nt2],     ah, kl0, kl1);
            MMA_BF16_2(sc[2 * nt2],     al, kh0, kh1);
            MMA_BF16_2(sc[2 * nt2 + 1], ah, kh2, kh3);
            MMA_BF16_2(sc[2 * nt2 + 1], ah, kl2, kl3);
            MMA_BF16_2(sc[2 * nt2 + 1], al, kh2, kh3);
        }
    }

    // ---- mask + scale (invalid -> -1e30 => exp==0, matches reference) ----
    const float scale = 0.17677669529663687f;   // 1/sqrt(32)
    const int sa = m0 + qr, sbr = sa + 8;
    const int sblka = sa / JOINTS, sblkb = sbr / JOINTS;
#pragma unroll
    for (int t = 0; t < 22; t++) {
        int t0 = t * 8 + qc, t1 = t0 + 1;
        int tb0 = t0 / JOINTS, tb1 = t1 / JOINTS;
        sc[t][0] = (tb0 != sblka || t0 == sa)  ? sc[t][0] * scale : -1e30f;
        sc[t][1] = (tb1 != sblka || t1 == sa)  ? sc[t][1] * scale : -1e30f;
        sc[t][2] = (tb0 != sblkb || t0 == sbr) ? sc[t][2] * scale : -1e30f;
        sc[t][3] = (tb1 != sblkb || t1 == sbr) ? sc[t][3] * scale : -1e30f;
    }
    float ma = -3.0e38f, mb = -3.0e38f;
#pragma unroll
    for (int t = 0; t < 22; t++) {
        ma = fmaxf(ma, fmaxf(sc[t][0], sc[t][1]));
        mb = fmaxf(mb, fmaxf(sc[t][2], sc[t][3]));
    }
    ma = fmaxf(ma, __shfl_xor_sync(0xffffffffu, ma, 1));
    ma = fmaxf(ma, __shfl_xor_sync(0xffffffffu, ma, 2));
    mb = fmaxf(mb, __shfl_xor_sync(0xffffffffu, mb, 1));
    mb = fmaxf(mb, __shfl_xor_sync(0xffffffffu, mb, 2));

    // ---- streaming exp -> split att frags -> att@V MMA (unnormalized) ----
    float D[4][4];
#pragma unroll
    for (int nt = 0; nt < 4; nt++)
#pragma unroll
        for (int r = 0; r < 4; r++) D[nt][r] = 0.0f;
    float suma = 0.0f, sumb = 0.0f;

#pragma unroll
    for (int j = 0; j < 11; j++) {
        float e[8];                      // tiles 2j (0..3), 2j+1 (4..7)
        e[0] = __expf(sc[2 * j][0] - ma);
        e[1] = __expf(sc[2 * j][1] - ma);
        e[2] = __expf(sc[2 * j][2] - mb);
        e[3] = __expf(sc[2 * j][3] - mb);
        e[4] = __expf(sc[2 * j + 1][0] - ma);
        e[5] = __expf(sc[2 * j + 1][1] - ma);
        e[6] = __expf(sc[2 * j + 1][2] - mb);
        e[7] = __expf(sc[2 * j + 1][3] - mb);
        suma += e[0] + e[1] + e[4] + e[5];
        sumb += e[2] + e[3] + e[6] + e[7];
        // A-frags: a0={r,k0..1} a1={r+8,k0..1} a2={r,k0+8..9} a3={r+8,k0+8..9}
        uint32_t af[4], alf[4];
        __nv_bfloat16 hh[8];
#pragma unroll
        for (int q = 0; q < 8; q++) hh[q] = __float2bfloat16(e[q]);
        af[0] = pk2(hh[0], hh[1]); af[1] = pk2(hh[2], hh[3]);
        af[2] = pk2(hh[4], hh[5]); af[3] = pk2(hh[6], hh[7]);
#pragma unroll
        for (int q = 0; q < 8; q++) hh[q] = __float2bfloat16(e[q] - __bfloat162float(hh[q]));
        alf[0] = pk2(hh[0], hh[1]); alf[1] = pk2(hh[2], hh[3]);
        alf[2] = pk2(hh[4], hh[5]); alf[3] = pk2(hh[6], hh[7]);
#pragma unroll
        for (int nh = 0; nh < 2; nh++) {
            uint32_t off = (uint32_t)((j * 16 + l16) * QS + nh * 16 + lhi * 8) * 2;
            uint32_t v0, v1, v2, v3, w0, w1, w2, w3;
            LDSM_X4_T(v0, v1, v2, v3, sb + VH_B + off);
            LDSM_X4_T(w0, w1, w2, w3, sb + VL_B + off);
            MMA_BF16_2(D[2 * nh],     af,  v0, v1);
            MMA_BF16_2(D[2 * nh],     af,  w0, w1);
            MMA_BF16_2(D[2 * nh],     alf, v0, v1);
            MMA_BF16_2(D[2 * nh + 1], af,  v2, v3);
            MMA_BF16_2(D[2 * nh + 1], af,  w2, w3);
            MMA_BF16_2(D[2 * nh + 1], alf, v2, v3);
        }
    }

    suma += __shfl_xor_sync(0xffffffffu, suma, 1);
    suma += __shfl_xor_sync(0xffffffffu, suma, 2);
    sumb += __shfl_xor_sync(0xffffffffu, sumb, 1);
    sumb += __shfl_xor_sync(0xffffffffu, sumb, 2);
    const float inva = 1.0f / suma, invb = 1.0f / sumb;

    // ---- write out[b, s, h*32 + d] (skip padded rows) ----
    float* ob = out + (size_t)b * SEQ * DMODEL + h * HDIM;
    if (sa < SEQ) {
#pragma unroll
        for (int nt = 0; nt < 4; nt++) {
            int d = nt * 8 + qc;
            float2 o; o.x = D[nt][0] * inva; o.y = D[nt][1] * inva;
            *(float2*)(ob + (size_t)sa * DMODEL + d) = o;
        }
    }
    if (sbr < SEQ) {
#pragma unroll
        for (int nt = 0; nt < 4; nt++) {
            int d = nt * 8 + qc;
            float2 o; o.x = D[nt][2] * invb; o.y = D[nt][3] * invb;
            *(float2*)(ob + (size_t)sbr * DMODEL + d) = o;
        }
    }
}

// ----------------------------------------------------------------------------
extern "C" void kernel_launch(void* const* d_in, const int* in_sizes, int n_in,
                              void* d_out, int out_size)
{
    const float* x  = (const float*)d_in[0];
    const float* Wq = (const float*)d_in[1];
    const float* bq = (const float*)d_in[2];
    const float* Wk = (const float*)d_in[3];
    const float* bk = (const float*)d_in[4];
    const float* Wv = (const float*)d_in[5];
    const float* bv = (const float*)d_in[6];
    float* out = (float*)d_out;

    cudaFuncSetAttribute(qkv_mma,
                         cudaFuncAttributeMaxDynamicSharedMemorySize, SM_QKV);
    cudaFuncSetAttribute(attn_mma,
                         cudaFuncAttributeMaxDynamicSharedMemorySize, SM_ATT);

    qkv_mma<<<dim3(MROWS / 128, 2, 3), 256, SM_QKV>>>(x, Wq, bq, Wk, bk, Wv, bv);
    attn_mma<<<BQ * HNUM, 384, SM_ATT>>>(out);
}

// round 13
// speedup vs baseline: 3.0156x; 1.3335x over previous
#include <cuda_runtime.h>
#include <cuda_bf16.h>
#include <cstdint>

// ----------------------------------------------------------------------------
// MultiHeadedAttention (temporal mask).
//   B=256, S=176 (8 time x 22 joints), D_in=128, H=8, Hd=32, D_model=256
// Kernel 0: prep_conv — x,W -> bf16 hi/lo gmem images (removes cvt from hot path)
// Kernel 1: qkv_mma   — mma.sync bf16-split GEMM, 128x64 tiles, 2 CTAs/SM
// Kernel 2: attn_mma  — FA-style tensor attention, 192-thr CTAs, 2 CTAs/SM
// ----------------------------------------------------------------------------

#define BQ      256
#define SEQ     176
#define DIN     128
#define DMODEL  256
#define HNUM    8
#define HDIM    32
#define MROWS   (BQ * SEQ)        // 45056
#define JOINTS  22

// Scratch (__device__ globals; no allocation allowed)
__device__ __align__(256) float gQ[BQ * HNUM * SEQ * HDIM];
__device__ __align__(256) float gK[BQ * HNUM * SEQ * HDIM];
__device__ __align__(256) float gV[BQ * HNUM * SEQ * HDIM];
__device__ __align__(16) __nv_bfloat16 gXhi[MROWS * DIN];    // 11.5 MB
__device__ __align__(16) __nv_bfloat16 gXlo[MROWS * DIN];
__device__ __align__(16) __nv_bfloat16 gWhi3[3 * DIN * DMODEL];
__device__ __align__(16) __nv_bfloat16 gWlo3[3 * DIN * DMODEL];

// ---------------- helpers ----------------
__device__ __forceinline__ uint32_t smem_u32(const void* p) {
    uint32_t a;
    asm("{ .reg .u64 t; cvta.to.shared.u64 t, %1; cvt.u32.u64 %0, t; }" : "=r"(a) : "l"(p));
    return a;
}
__device__ __forceinline__ uint32_t pk2(__nv_bfloat16 a, __nv_bfloat16 b) {
    return (uint32_t)__bfloat16_as_ushort(a) | ((uint32_t)__bfloat16_as_ushort(b) << 16);
}
__device__ __forceinline__ void split4(float4 v, uint2& hi, uint2& lo) {
    __nv_bfloat16 h0 = __float2bfloat16(v.x), h1 = __float2bfloat16(v.y);
    __nv_bfloat16 h2 = __float2bfloat16(v.z), h3 = __float2bfloat16(v.w);
    hi.x = pk2(h0, h1); hi.y = pk2(h2, h3);
    lo.x = pk2(__float2bfloat16(v.x - __bfloat162float(h0)),
               __float2bfloat16(v.y - __bfloat162float(h1)));
    lo.y = pk2(__float2bfloat16(v.z - __bfloat162float(h2)),
               __float2bfloat16(v.w - __bfloat162float(h3)));
}

#define LDSM_X4(r0, r1, r2, r3, addr)                                           \
    asm volatile("ldmatrix.sync.aligned.m8n8.x4.shared.b16 {%0,%1,%2,%3}, [%4];" \
        : "=r"(r0), "=r"(r1), "=r"(r2), "=r"(r3) : "r"(addr))
#define LDSM_X4_T(r0, r1, r2, r3, addr)                                         \
    asm volatile("ldmatrix.sync.aligned.m8n8.x4.trans.shared.b16 {%0,%1,%2,%3}, [%4];" \
        : "=r"(r0), "=r"(r1), "=r"(r2), "=r"(r3) : "r"(addr))

#define MMA_BF16(d, a, b)                                                       \
    asm volatile("mma.sync.aligned.m16n8k16.row.col.f32.bf16.bf16.f32 "         \
        "{%0,%1,%2,%3}, {%4,%5,%6,%7}, {%8,%9}, {%0,%1,%2,%3};"                 \
        : "+f"((d)[0]), "+f"((d)[1]), "+f"((d)[2]), "+f"((d)[3])                \
        : "r"((a)[0]), "r"((a)[1]), "r"((a)[2]), "r"((a)[3]),                   \
          "r"((b)[0]), "r"((b)[1]))
#define MMA_BF16_2(d, a, b0, b1)                                                \
    asm volatile("mma.sync.aligned.m16n8k16.row.col.f32.bf16.bf16.f32 "         \
        "{%0,%1,%2,%3}, {%4,%5,%6,%7}, {%8,%9}, {%0,%1,%2,%3};"                 \
        : "+f"((d)[0]), "+f"((d)[1]), "+f"((d)[2]), "+f"((d)[3])                \
        : "r"((a)[0]), "r"((a)[1]), "r"((a)[2]), "r"((a)[3]),                   \
          "r"(b0), "r"(b1))

// ----------------------------------------------------------------------------
// Kernel 0: convert x and W to bf16 hi/lo images in gmem.
// ----------------------------------------------------------------------------
#define XQUADS (MROWS * DIN / 4)       // 1441792
#define WQUADS (3 * DIN * DMODEL / 4)  // 24576

__global__ __launch_bounds__(256) void prep_conv(
    const float* __restrict__ x,  const float* __restrict__ Wq,
    const float* __restrict__ Wk, const float* __restrict__ Wv)
{
    int idx = blockIdx.x * 256 + threadIdx.x;
    if (idx < XQUADS) {
        uint2 hi, lo;
        split4(((const float4*)x)[idx], hi, lo);
        ((uint2*)gXhi)[idx] = hi;
        ((uint2*)gXlo)[idx] = lo;
    } else {
        int w = idx - XQUADS;
        if (w < WQUADS) {
            int z = w / (DIN * DMODEL / 4);
            int r = w - z * (DIN * DMODEL / 4);
            const float* W = (z == 0) ? Wq : ((z == 1) ? Wk : Wv);
            uint2 hi, lo;
            split4(((const float4*)W)[r], hi, lo);
            ((uint2*)gWhi3)[w] = hi;
            ((uint2*)gWlo3)[w] = lo;
        }
    }
}

// ----------------------------------------------------------------------------
// Kernel 1: QKV GEMM. grid=(352,4,3), block=256 (8 warps: 4 wr x 2 wc),
// tile 128 rows x 64 cols, K=128. smem 104448B -> 2 CTAs/SM.
// ----------------------------------------------------------------------------
#define AS 136                          // A stride (272B = 16 mod 128) cf-free
#define BS2 72                          // B stride (144B = 16 mod 128) cf-free
#define SM_AHI  0
#define SM_ALO  (SM_AHI + 128 * AS * 2)      // 34816
#define SM_BHI  (SM_ALO + 128 * AS * 2)      // 69632
#define SM_BLO  (SM_BHI + 128 * BS2 * 2)     // 88064
#define SM_QKV  (SM_BLO + 128 * BS2 * 2)     // 106496

__global__ __launch_bounds__(256, 2) void qkv_mma(
    const float* __restrict__ bq, const float* __restrict__ bk,
    const float* __restrict__ bv)
{
    extern __shared__ char smem[];
    const uint32_t sb = smem_u32(smem);
    const int tid  = threadIdx.x;
    const int wid  = tid >> 5;
    const int lane = tid & 31;
    const int wr   = wid >> 1;          // 0..3 (32 rows each)
    const int wc   = wid & 1;           // 0..1 (32 cols each)
    const int z    = blockIdx.z;
    const int rm   = blockIdx.x * 128;
    const int cn   = blockIdx.y * 64;

    const float* __restrict__ bias = (z == 0) ? bq : ((z == 1) ? bk : bv);
    float* __restrict__ outp       = (z == 0) ? gQ : ((z == 1) ? gK : gV);

    // ---- stage A (16B copies from preconverted images) ----
#pragma unroll
    for (int i = tid; i < 2048; i += 256) {       // 128 rows x 16 uint4
        int row = i >> 4, c = i & 15;
        size_t src = (size_t)(rm + row) * DIN + c * 8;
        uint32_t dst = (uint32_t)(row * AS + c * 8) * 2;
        *(uint4*)(smem + SM_AHI + dst) = *(const uint4*)(gXhi + src);
        *(uint4*)(smem + SM_ALO + dst) = *(const uint4*)(gXlo + src);
    }
    // ---- stage B ----
#pragma unroll
    for (int i = tid; i < 1024; i += 256) {       // 128 rows x 8 uint4
        int row = i >> 3, c = i & 7;
        size_t src = ((size_t)z * DIN + row) * DMODEL + cn + c * 8;
        uint32_t dst = (uint32_t)(row * BS2 + c * 8) * 2;
        *(uint4*)(smem + SM_BHI + dst) = *(const uint4*)(gWhi3 + src);
        *(uint4*)(smem + SM_BLO + dst) = *(const uint4*)(gWlo3 + src);
    }
    __syncthreads();

    float acc[2][4][4];
#pragma unroll
    for (int mt = 0; mt < 2; mt++)
#pragma unroll
        for (int nt = 0; nt < 4; nt++)
#pragma unroll
            for (int r = 0; r < 4; r++) acc[mt][nt][r] = 0.0f;

    const int l16 = lane & 15, lhi = lane >> 4;
    const int m0 = wr * 32, n0 = wc * 32;

#pragma unroll
    for (int ks = 0; ks < 8; ks++) {
        uint32_t ah[2][4], al[2][4];
#pragma unroll
        for (int mt = 0; mt < 2; mt++) {
            uint32_t off = (uint32_t)((m0 + mt * 16 + l16) * AS + ks * 16 + lhi * 8) * 2;
            LDSM_X4(ah[mt][0], ah[mt][1], ah[mt][2], ah[mt][3], sb + SM_AHI + off);
            LDSM_X4(al[mt][0], al[mt][1], al[mt][2], al[mt][3], sb + SM_ALO + off);
        }
        uint32_t bh[4][2], bl[4][2];
#pragma unroll
        for (int p = 0; p < 2; p++) {
            uint32_t off = (uint32_t)((ks * 16 + l16) * BS2 + n0 + p * 16 + lhi * 8) * 2;
            uint32_t r0, r1, r2, r3;
            LDSM_X4_T(r0, r1, r2, r3, sb + SM_BHI + off);
            bh[p * 2][0] = r0; bh[p * 2][1] = r1;
            bh[p * 2 + 1][0] = r2; bh[p * 2 + 1][1] = r3;
            LDSM_X4_T(r0, r1, r2, r3, sb + SM_BLO + off);
            bl[p * 2][0] = r0; bl[p * 2][1] = r1;
            bl[p * 2 + 1][0] = r2; bl[p * 2 + 1][1] = r3;
        }
#pragma unroll
        for (int mt = 0; mt < 2; mt++)
#pragma unroll
            for (int nt = 0; nt < 4; nt++) {
                MMA_BF16(acc[mt][nt], ah[mt], bh[nt]);
                MMA_BF16(acc[mt][nt], ah[mt], bl[nt]);
                MMA_BF16(acc[mt][nt], al[mt], bh[nt]);
            }
    }

    // ---- epilogue: bias (+ReLU for V), scatter to [B,H,S,32] ----
    const int col0 = cn + wc * 32;      // multiple of 32 -> one head
    const int h    = col0 >> 5;
    const int l4r  = lane >> 2;
    const int l4c  = (lane & 3) << 1;
#pragma unroll
    for (int mt = 0; mt < 2; mt++) {
#pragma unroll
        for (int nt = 0; nt < 4; nt++) {
            int d = nt * 8 + l4c;
            float2 bb = *(const float2*)(bias + col0 + d);
            int g0 = rm + wr * 32 + mt * 16 + l4r;
            int b0 = g0 / SEQ, s0 = g0 - b0 * SEQ;
            int g1 = g0 + 8;
            int b1 = g1 / SEQ, s1 = g1 - b1 * SEQ;
            float2 o0, o1;
            o0.x = acc[mt][nt][0] + bb.x; o0.y = acc[mt][nt][1] + bb.y;
            o1.x = acc[mt][nt][2] + bb.x; o1.y = acc[mt][nt][3] + bb.y;
            if (z == 2) {
                o0.x = fmaxf(o0.x, 0.0f); o0.y = fmaxf(o0.y, 0.0f);
                o1.x = fmaxf(o1.x, 0.0f); o1.y = fmaxf(o1.y, 0.0f);
            }
            *(float2*)(outp + (((size_t)(b0 * HNUM + h)) * SEQ + s0) * HDIM + d) = o0;
            *(float2*)(outp + (((size_t)(b1 * HNUM + h)) * SEQ + s1) * HDIM + d) = o1;
        }
    }
}

// ----------------------------------------------------------------------------
// Kernel 2: tensor-core attention. grid=4096 (bh x 2 halves), block=192
// (6 warps x m16 = 96 q-rows). smem 67072B, <=168 regs -> 2 CTAs/SM.
// ----------------------------------------------------------------------------
#define QS   40                        // 80B stride, cf-free
#define KTS  184                       // 368B stride, cf-free
#define QH_B 0
#define QL_B (QH_B + 96 * QS * 2)      // 7680
#define VH_B (QL_B + 96 * QS * 2)      // 15360
#define VL_B (VH_B + 176 * QS * 2)     // 29440
#define KH_B (VL_B + 176 * QS * 2)     // 43520
#define KL_B (KH_B + 32 * KTS * 2)     // 55296
#define SM_ATT (KL_B + 32 * KTS * 2)   // 67072 bytes

__global__ __launch_bounds__(192, 2) void attn_mma(float* __restrict__ out)
{
    extern __shared__ char smem[];
    const uint32_t sb = smem_u32(smem);
    const int bh   = blockIdx.x >> 1;
    const int half = blockIdx.x & 1;
    const int b  = bh >> 3;
    const int h  = bh & 7;
    const size_t base = (size_t)bh * SEQ * HDIM;
    const float* __restrict__ Qb = gQ + base;
    const float* __restrict__ Kb = gK + base;
    const float* __restrict__ Vb = gV + base;
    const int tid = threadIdx.x;

    // ---- stage this half's Q rows (zero-padded >=176), full V, full Kt ----
#pragma unroll
    for (int i = tid; i < 96 * 8; i += 192) {
        int row = i >> 3, d4 = (i & 7) << 2;
        int gr = half * 96 + row;
        float4 v = (gr < SEQ) ? *(const float4*)(Qb + gr * HDIM + d4)
                              : make_float4(0.f, 0.f, 0.f, 0.f);
        uint2 hi, lo; split4(v, hi, lo);
        uint32_t off = (uint32_t)(row * QS + d4) * 2;
        *(uint2*)(smem + QH_B + off) = hi;
        *(uint2*)(smem + QL_B + off) = lo;
    }
#pragma unroll
    for (int i = tid; i < 176 * 8; i += 192) {
        int row = i >> 3, d4 = (i & 7) << 2;
        float4 v = *(const float4*)(Vb + row * HDIM + d4);
        uint2 hi, lo; split4(v, hi, lo);
        uint32_t off = (uint32_t)(row * QS + d4) * 2;
        *(uint2*)(smem + VH_B + off) = hi;
        *(uint2*)(smem + VL_B + off) = lo;
    }
#pragma unroll
    for (int i = tid; i < 176 * 32; i += 192) {
        int t = i >> 5, d = i & 31;
        float kv = Kb[i];
        __nv_bfloat16 kh = __float2bfloat16(kv);
        __nv_bfloat16 kl = __float2bfloat16(kv - __bfloat162float(kh));
        ((__nv_bfloat16*)(smem + KH_B))[d * KTS + t] = kh;
        ((__nv_bfloat16*)(smem + KL_B))[d * KTS + t] = kl;
    }
    __syncthreads();

    const int warp = tid >> 5, lane = tid & 31;
    const int m0  = warp * 16;          // local row tile
    const int l16 = lane & 15, lhi = lane >> 4;
    const int qr  = lane >> 2, qc = (lane & 3) << 1;

    // ---- scores: 3-term split MMA ----
    float sc[22][4];
#pragma unroll
    for (int t = 0; t < 22; t++)
#pragma unroll
        for (int r = 0; r < 4; r++) sc[t][r] = 0.0f;

#pragma unroll
    for (int ks = 0; ks < 2; ks++) {
        uint32_t ah[4], al[4];
        uint32_t aoff = (uint32_t)((m0 + l16) * QS + ks * 16 + lhi * 8) * 2;
        LDSM_X4(ah[0], ah[1], ah[2], ah[3], sb + QH_B + aoff);
        LDSM_X4(al[0], al[1], al[2], al[3], sb + QL_B + aoff);
#pragma unroll
        for (int nt2 = 0; nt2 < 11; nt2++) {
            uint32_t boff = (uint32_t)((ks * 16 + l16) * KTS + nt2 * 16 + lhi * 8) * 2;
            uint32_t kh0, kh1, kh2, kh3, kl0, kl1, kl2, kl3;
            LDSM_X4_T(kh0, kh1, kh2, kh3, sb + KH_B + boff);
            LDSM_X4_T(kl0, kl1, kl2, kl3, sb + KL_B + boff);
            MMA_BF16_2(sc[2 * nt2],     ah, kh0, kh1);
            MMA_BF16_2(sc[2 * nt2],     ah, kl0, kl1);
            MMA_BF16_2(sc[2 * nt2],     al, kh0, kh1);
            MMA_BF16_2(sc[2 * nt2 + 1], ah, kh2, kh3);
            MMA_BF16_2(sc[2 * nt2 + 1], ah, kl2, kl3);
            MMA_BF16_2(sc[2 * nt2 + 1], al, kh2, kh3);
        }
    }

    // ---- mask (range compare) + scale; invalid -> -1e30 (exp==0) ----
    const float scale = 0.17677669529663687f;   // 1/sqrt(32)
    const int sa  = half * 96 + m0 + qr;
    const int sbr = sa + 8;
    const int loa = (sa / JOINTS) * JOINTS,  hia = loa + JOINTS;
    const int lob = (sbr / JOINTS) * JOINTS, hib = lob + JOINTS;
#pragma unroll
    for (int t = 0; t < 22; t++) {
        int t0 = t * 8 + qc, t1 = t0 + 1;
        sc[t][0] = (t0 < loa || t0 >= hia || t0 == sa)  ? sc[t][0] * scale : -1e30f;
        sc[t][1] = (t1 < loa || t1 >= hia || t1 == sa)  ? sc[t][1] * scale : -1e30f;
        sc[t][2] = (t0 < lob || t0 >= hib || t0 == sbr) ? sc[t][2] * scale : -1e30f;
        sc[t][3] = (t1 < lob || t1 >= hib || t1 == sbr) ? sc[t][3] * scale : -1e30f;
    }
    float ma = -3.0e38f, mb = -3.0e38f;
#pragma unroll
    for (int t = 0; t < 22; t++) {
        ma = fmaxf(ma, fmaxf(sc[t][0], sc[t][1]));
        mb = fmaxf(mb, fmaxf(sc[t][2], sc[t][3]));
    }
    ma = fmaxf(ma, __shfl_xor_sync(0xffffffffu, ma, 1));
    ma = fmaxf(ma, __shfl_xor_sync(0xffffffffu, ma, 2));
    mb = fmaxf(mb, __shfl_xor_sync(0xffffffffu, mb, 1));
    mb = fmaxf(mb, __shfl_xor_sync(0xffffffffu, mb, 2));

    // ---- streaming exp -> split att frags -> att@V (unnormalized) ----
    float D[4][4];
#pragma unroll
    for (int nt = 0; nt < 4; nt++)
#pragma unroll
        for (int r = 0; r < 4; r++) D[nt][r] = 0.0f;
    float suma = 0.0f, sumb = 0.0f;

#pragma unroll
    for (int j = 0; j < 11; j++) {
        float e[8];
        e[0] = __expf(sc[2 * j][0] - ma);
        e[1] = __expf(sc[2 * j][1] - ma);
        e[2] = __expf(sc[2 * j][2] - mb);
        e[3] = __expf(sc[2 * j][3] - mb);
        e[4] = __expf(sc[2 * j + 1][0] - ma);
        e[5] = __expf(sc[2 * j + 1][1] - ma);
        e[6] = __expf(sc[2 * j + 1][2] - mb);
        e[7] = __expf(sc[2 * j + 1][3] - mb);
        suma += e[0] + e[1] + e[4] + e[5];
        sumb += e[2] + e[3] + e[6] + e[7];
        uint32_t af[4], alf[4];
        __nv_bfloat16 hh[8];
#pragma unroll
        for (int q = 0; q < 8; q++) hh[q] = __float2bfloat16(e[q]);
        af[0] = pk2(hh[0], hh[1]); af[1] = pk2(hh[2], hh[3]);
        af[2] = pk2(hh[4], hh[5]); af[3] = pk2(hh[6], hh[7]);
#pragma unroll
        for (int q = 0; q < 8; q++) hh[q] = __float2bfloat16(e[q] - __bfloat162float(hh[q]));
        alf[0] = pk2(hh[0], hh[1]); alf[1] = pk2(hh[2], hh[3]);
        alf[2] = pk2(hh[4], hh[5]); alf[3] = pk2(hh[6], hh[7]);
#pragma unroll
        for (int nh = 0; nh < 2; nh++) {
            uint32_t off = (uint32_t)((j * 16 + l16) * QS + nh * 16 + lhi * 8) * 2;
            uint32_t v0, v1, v2, v3, w0, w1, w2, w3;
            LDSM_X4_T(v0, v1, v2, v3, sb + VH_B + off);
            LDSM_X4_T(w0, w1, w2, w3, sb + VL_B + off);
            MMA_BF16_2(D[2 * nh],     af,  v0, v1);
            MMA_BF16_2(D[2 * nh],     af,  w0, w1);
            MMA_BF16_2(D[2 * nh],     alf, v0, v1);
            MMA_BF16_2(D[2 * nh + 1], af,  v2, v3);
            MMA_BF16_2(D[2 * nh + 1], af,  w2, w3);
            MMA_BF16_2(D[2 * nh + 1], alf, v2, v3);
        }
    }

    suma += __shfl_xor_sync(0xffffffffu, suma, 1);
    suma += __shfl_xor_sync(0xffffffffu, suma, 2);
    sumb += __shfl_xor_sync(0xffffffffu, sumb, 1);
    sumb += __shfl_xor_sync(0xffffffffu, sumb, 2);
    const float inva = 1.0f / suma, invb = 1.0f / sumb;

    float* ob = out + (size_t)b * SEQ * DMODEL + h * HDIM;
    if (sa < SEQ) {
#pragma unroll
        for (int nt = 0; nt < 4; nt++) {
            int d = nt * 8 + qc;
            float2 o; o.x = D[nt][0] * inva; o.y = D[nt][1] * inva;
            *(float2*)(ob + (size_t)sa * DMODEL + d) = o;
        }
    }
    if (sbr < SEQ) {
#pragma unroll
        for (int nt = 0; nt < 4; nt++) {
            int d = nt * 8 + qc;
            float2 o; o.x = D[nt][2] * invb; o.y = D[nt][3] * invb;
            *(float2*)(ob + (size_t)sbr * DMODEL + d) = o;
        }
    }
}

// ----------------------------------------------------------------------------
extern "C" void kernel_launch(void* const* d_in, const int* in_sizes, int n_in,
                              void* d_out, int out_size)
{
    const float* x  = (const float*)d_in[0];
    const float* Wq = (const float*)d_in[1];
    const float* bq = (const float*)d_in[2];
    const float* Wk = (const float*)d_in[3];
    const float* bk = (const float*)d_in[4];
    const float* Wv = (const float*)d_in[5];
    const float* bv = (const float*)d_in[6];
    float* out = (float*)d_out;

    cudaFuncSetAttribute(qkv_mma,
                         cudaFuncAttributeMaxDynamicSharedMemorySize, SM_QKV);
    cudaFuncSetAttribute(attn_mma,
                         cudaFuncAttributeMaxDynamicSharedMemorySize, SM_ATT);

    const int prep_blocks = (XQUADS + WQUADS + 255) / 256;
    prep_conv<<<prep_blocks, 256>>>(x, Wq, Wk, Wv);
    qkv_mma<<<dim3(MROWS / 128, DMODEL / 64, 3), 256, SM_QKV>>>(bq, bk, bv);
    attn_mma<<<BQ * HNUM * 2, 192, SM_ATT>>>(out);
}

// round 14
// speedup vs baseline: 3.0397x; 1.0080x over previous
#include <cuda_runtime.h>
#include <cuda_bf16.h>
#include <cstdint>

// ----------------------------------------------------------------------------
// MultiHeadedAttention (temporal mask).
//   B=256, S=176 (8 time x 22 joints), D_in=128, H=8, Hd=32, D_model=256
// Kernel 0: prep_conv — x,W -> bf16 hi/lo gmem images
// Kernel 1: qkv_mma   — bf16-split GEMM; epilogue emits bf16 hi/lo Q,V and
//                       PRE-TRANSPOSED K, so attn staging is pure copies
// Kernel 2: attn_mma  — FA-style tensor attention, copy-only staging, no-max
//                       softmax (masked = -1e30 -> expf==0)
// ----------------------------------------------------------------------------

#define BQ      256
#define SEQ     176
#define DIN     128
#define DMODEL  256
#define HNUM    8
#define HDIM    32
#define MROWS   (BQ * SEQ)        // 45056
#define JOINTS  22
#define BHSZ    (SEQ * HDIM)      // 5632

// Scratch (__device__ globals; no allocation allowed)
__device__ __align__(16) __nv_bfloat16 gXhi[MROWS * DIN];
__device__ __align__(16) __nv_bfloat16 gXlo[MROWS * DIN];
__device__ __align__(16) __nv_bfloat16 gWhi3[3 * DIN * DMODEL];
__device__ __align__(16) __nv_bfloat16 gWlo3[3 * DIN * DMODEL];
// bf16 hi/lo Q,V: [bh][s][32];  K transposed: [bh][d=32][t=176]
__device__ __align__(16) __nv_bfloat16 gQh[BQ * HNUM * BHSZ];
__device__ __align__(16) __nv_bfloat16 gQl[BQ * HNUM * BHSZ];
__device__ __align__(16) __nv_bfloat16 gVh[BQ * HNUM * BHSZ];
__device__ __align__(16) __nv_bfloat16 gVl[BQ * HNUM * BHSZ];
__device__ __align__(16) __nv_bfloat16 gKth[BQ * HNUM * BHSZ];
__device__ __align__(16) __nv_bfloat16 gKtl[BQ * HNUM * BHSZ];

// ---------------- helpers ----------------
__device__ __forceinline__ uint32_t smem_u32(const void* p) {
    uint32_t a;
    asm("{ .reg .u64 t; cvta.to.shared.u64 t, %1; cvt.u32.u64 %0, t; }" : "=r"(a) : "l"(p));
    return a;
}
__device__ __forceinline__ uint32_t pk2(__nv_bfloat16 a, __nv_bfloat16 b) {
    return (uint32_t)__bfloat16_as_ushort(a) | ((uint32_t)__bfloat16_as_ushort(b) << 16);
}
__device__ __forceinline__ void split4(float4 v, uint2& hi, uint2& lo) {
    __nv_bfloat16 h0 = __float2bfloat16(v.x), h1 = __float2bfloat16(v.y);
    __nv_bfloat16 h2 = __float2bfloat16(v.z), h3 = __float2bfloat16(v.w);
    hi.x = pk2(h0, h1); hi.y = pk2(h2, h3);
    lo.x = pk2(__float2bfloat16(v.x - __bfloat162float(h0)),
               __float2bfloat16(v.y - __bfloat162float(h1)));
    lo.y = pk2(__float2bfloat16(v.z - __bfloat162float(h2)),
               __float2bfloat16(v.w - __bfloat162float(h3)));
}

#define LDSM_X4(r0, r1, r2, r3, addr)                                           \
    asm volatile("ldmatrix.sync.aligned.m8n8.x4.shared.b16 {%0,%1,%2,%3}, [%4];" \
        : "=r"(r0), "=r"(r1), "=r"(r2), "=r"(r3) : "r"(addr))
#define LDSM_X4_T(r0, r1, r2, r3, addr)                                         \
    asm volatile("ldmatrix.sync.aligned.m8n8.x4.trans.shared.b16 {%0,%1,%2,%3}, [%4];" \
        : "=r"(r0), "=r"(r1), "=r"(r2), "=r"(r3) : "r"(addr))

#define MMA_BF16(d, a, b)                                                       \
    asm volatile("mma.sync.aligned.m16n8k16.row.col.f32.bf16.bf16.f32 "         \
        "{%0,%1,%2,%3}, {%4,%5,%6,%7}, {%8,%9}, {%0,%1,%2,%3};"                 \
        : "+f"((d)[0]), "+f"((d)[1]), "+f"((d)[2]), "+f"((d)[3])                \
        : "r"((a)[0]), "r"((a)[1]), "r"((a)[2]), "r"((a)[3]),                   \
          "r"((b)[0]), "r"((b)[1]))
#define MMA_BF16_2(d, a, b0, b1)                                                \
    asm volatile("mma.sync.aligned.m16n8k16.row.col.f32.bf16.bf16.f32 "         \
        "{%0,%1,%2,%3}, {%4,%5,%6,%7}, {%8,%9}, {%0,%1,%2,%3};"                 \
        : "+f"((d)[0]), "+f"((d)[1]), "+f"((d)[2]), "+f"((d)[3])                \
        : "r"((a)[0]), "r"((a)[1]), "r"((a)[2]), "r"((a)[3]),                   \
          "r"(b0), "r"(b1))

// ----------------------------------------------------------------------------
// Kernel 0: convert x and W to bf16 hi/lo images in gmem.
// ----------------------------------------------------------------------------
#define XQUADS (MROWS * DIN / 4)
#define WQUADS (3 * DIN * DMODEL / 4)

__global__ __launch_bounds__(256) void prep_conv(
    const float* __restrict__ x,  const float* __restrict__ Wq,
    const float* __restrict__ Wk, const float* __restrict__ Wv)
{
    int idx = blockIdx.x * 256 + threadIdx.x;
    if (idx < XQUADS) {
        uint2 hi, lo;
        split4(((const float4*)x)[idx], hi, lo);
        ((uint2*)gXhi)[idx] = hi;
        ((uint2*)gXlo)[idx] = lo;
    } else {
        int w = idx - XQUADS;
        if (w < WQUADS) {
            int z = w / (DIN * DMODEL / 4);
            int r = w - z * (DIN * DMODEL / 4);
            const float* W = (z == 0) ? Wq : ((z == 1) ? Wk : Wv);
            uint2 hi, lo;
            split4(((const float4*)W)[r], hi, lo);
            ((uint2*)gWhi3)[w] = hi;
            ((uint2*)gWlo3)[w] = lo;
        }
    }
}

// ----------------------------------------------------------------------------
// Kernel 1: QKV GEMM. grid=(352,4,3), block=256 (8 warps: 4 wr x 2 wc),
// tile 128 rows x 64 cols, K=128. 2 CTAs/SM.
// ----------------------------------------------------------------------------
#define AS 136
#define BS2 72
#define SM_AHI  0
#define SM_ALO  (SM_AHI + 128 * AS * 2)
#define SM_BHI  (SM_ALO + 128 * AS * 2)
#define SM_BLO  (SM_BHI + 128 * BS2 * 2)
#define SM_QKV  (SM_BLO + 128 * BS2 * 2)     // 106496

__global__ __launch_bounds__(256, 2) void qkv_mma(
    const float* __restrict__ bq, const float* __restrict__ bk,
    const float* __restrict__ bv)
{
    extern __shared__ char smem[];
    const uint32_t sb = smem_u32(smem);
    const int tid  = threadIdx.x;
    const int wid  = tid >> 5;
    const int lane = tid & 31;
    const int wr   = wid >> 1;
    const int wc   = wid & 1;
    const int z    = blockIdx.z;
    const int rm   = blockIdx.x * 128;
    const int cn   = blockIdx.y * 64;

    const float* __restrict__ bias = (z == 0) ? bq : ((z == 1) ? bk : bv);

#pragma unroll
    for (int i = tid; i < 2048; i += 256) {
        int row = i >> 4, c = i & 15;
        size_t src = (size_t)(rm + row) * DIN + c * 8;
        uint32_t dst = (uint32_t)(row * AS + c * 8) * 2;
        *(uint4*)(smem + SM_AHI + dst) = *(const uint4*)(gXhi + src);
        *(uint4*)(smem + SM_ALO + dst) = *(const uint4*)(gXlo + src);
    }
#pragma unroll
    for (int i = tid; i < 1024; i += 256) {
        int row = i >> 3, c = i & 7;
        size_t src = ((size_t)z * DIN + row) * DMODEL + cn + c * 8;
        uint32_t dst = (uint32_t)(row * BS2 + c * 8) * 2;
        *(uint4*)(smem + SM_BHI + dst) = *(const uint4*)(gWhi3 + src);
        *(uint4*)(smem + SM_BLO + dst) = *(const uint4*)(gWlo3 + src);
    }
    __syncthreads();

    float acc[2][4][4];
#pragma unroll
    for (int mt = 0; mt < 2; mt++)
#pragma unroll
        for (int nt = 0; nt < 4; nt++)
#pragma unroll
            for (int r = 0; r < 4; r++) acc[mt][nt][r] = 0.0f;

    const int l16 = lane & 15, lhi = lane >> 4;
    const int m0 = wr * 32, n0 = wc * 32;

#pragma unroll
    for (int ks = 0; ks < 8; ks++) {
        uint32_t ah[2][4], al[2][4];
#pragma unroll
        for (int mt = 0; mt < 2; mt++) {
            uint32_t off = (uint32_t)((m0 + mt * 16 + l16) * AS + ks * 16 + lhi * 8) * 2;
            LDSM_X4(ah[mt][0], ah[mt][1], ah[mt][2], ah[mt][3], sb + SM_AHI + off);
            LDSM_X4(al[mt][0], al[mt][1], al[mt][2], al[mt][3], sb + SM_ALO + off);
        }
        uint32_t bh[4][2], bl[4][2];
#pragma unroll
        for (int p = 0; p < 2; p++) {
            uint32_t off = (uint32_t)((ks * 16 + l16) * BS2 + n0 + p * 16 + lhi * 8) * 2;
            uint32_t r0, r1, r2, r3;
            LDSM_X4_T(r0, r1, r2, r3, sb + SM_BHI + off);
            bh[p * 2][0] = r0; bh[p * 2][1] = r1;
            bh[p * 2 + 1][0] = r2; bh[p * 2 + 1][1] = r3;
            LDSM_X4_T(r0, r1, r2, r3, sb + SM_BLO + off);
            bl[p * 2][0] = r0; bl[p * 2][1] = r1;
            bl[p * 2 + 1][0] = r2; bl[p * 2 + 1][1] = r3;
        }
#pragma unroll
        for (int mt = 0; mt < 2; mt++)
#pragma unroll
            for (int nt = 0; nt < 4; nt++) {
                MMA_BF16(acc[mt][nt], ah[mt], bh[nt]);
                MMA_BF16(acc[mt][nt], ah[mt], bl[nt]);
                MMA_BF16(acc[mt][nt], al[mt], bh[nt]);
            }
    }

    // ---- epilogue: bias (+ReLU for V), emit bf16 hi/lo; K pre-transposed ----
    const int col0 = cn + wc * 32;      // one head per 32-col chunk
    const int h    = col0 >> 5;
    const int l4r  = lane >> 2;
    const int l4c  = (lane & 3) << 1;
#pragma unroll
    for (int mt = 0; mt < 2; mt++) {
#pragma unroll
        for (int nt = 0; nt < 4; nt++) {
            int d = nt * 8 + l4c;
            float2 bb = *(const float2*)(bias + col0 + d);
            int g0 = rm + wr * 32 + mt * 16 + l4r;
            int b0 = g0 / SEQ, s0 = g0 - b0 * SEQ;
            int g1 = g0 + 8;
            int b1 = g1 / SEQ, s1 = g1 - b1 * SEQ;
            float ox0 = acc[mt][nt][0] + bb.x, oy0 = acc[mt][nt][1] + bb.y;
            float ox1 = acc[mt][nt][2] + bb.x, oy1 = acc[mt][nt][3] + bb.y;
            if (z == 2) {
                ox0 = fmaxf(ox0, 0.0f); oy0 = fmaxf(oy0, 0.0f);
                ox1 = fmaxf(ox1, 0.0f); oy1 = fmaxf(oy1, 0.0f);
            }
            __nv_bfloat16 hx0 = __float2bfloat16(ox0), hy0 = __float2bfloat16(oy0);
            __nv_bfloat16 hx1 = __float2bfloat16(ox1), hy1 = __float2bfloat16(oy1);
            __nv_bfloat16 lx0 = __float2bfloat16(ox0 - __bfloat162float(hx0));
            __nv_bfloat16 ly0 = __float2bfloat16(oy0 - __bfloat162float(hy0));
            __nv_bfloat16 lx1 = __float2bfloat16(ox1 - __bfloat162float(hx1));
            __nv_bfloat16 ly1 = __float2bfloat16(oy1 - __bfloat162float(hy1));
            if (z != 1) {
                __nv_bfloat16* oh = (z == 0) ? gQh : gVh;
                __nv_bfloat16* ol = (z == 0) ? gQl : gVl;
                size_t o0 = ((size_t)(b0 * HNUM + h) * SEQ + s0) * HDIM + d;
                size_t o1 = ((size_t)(b1 * HNUM + h) * SEQ + s1) * HDIM + d;
                *(uint32_t*)(oh + o0) = pk2(hx0, hy0);
                *(uint32_t*)(ol + o0) = pk2(lx0, ly0);
                *(uint32_t*)(oh + o1) = pk2(hx1, hy1);
                *(uint32_t*)(ol + o1) = pk2(lx1, ly1);
            } else {
                size_t k0 = (size_t)(b0 * HNUM + h) * BHSZ + d * SEQ + s0;
                size_t k1 = (size_t)(b1 * HNUM + h) * BHSZ + d * SEQ + s1;
                gKth[k0] = hx0; gKth[k0 + SEQ] = hy0;
                gKtl[k0] = lx0; gKtl[k0 + SEQ] = ly0;
                gKth[k1] = hx1; gKth[k1 + SEQ] = hy1;
                gKtl[k1] = lx1; gKtl[k1 + SEQ] = ly1;
            }
        }
    }
}

// ----------------------------------------------------------------------------
// Kernel 2: tensor-core attention. grid=4096 (bh x 2 halves), block=192
// (6 warps x m16 = 96 q-rows). Copy-only staging; no-max softmax.
// ----------------------------------------------------------------------------
#define QS   40
#define KTS  184
#define QH_B 0
#define QL_B (QH_B + 96 * QS * 2)
#define VH_B (QL_B + 96 * QS * 2)
#define VL_B (VH_B + 176 * QS * 2)
#define KH_B (VL_B + 176 * QS * 2)
#define KL_B (KH_B + 32 * KTS * 2)
#define SM_ATT (KL_B + 32 * KTS * 2)   // 67072 bytes

__global__ __launch_bounds__(192, 2) void attn_mma(float* __restrict__ out)
{
    extern __shared__ char smem[];
    const uint32_t sb = smem_u32(smem);
    const int bh   = blockIdx.x >> 1;
    const int half = blockIdx.x & 1;
    const int b  = bh >> 3;
    const int h  = bh & 7;
    const size_t base = (size_t)bh * BHSZ;
    const int tid = threadIdx.x;

    // ---- staging: pure 16B copies ----
#pragma unroll
    for (int i = tid; i < 96 * 4; i += 192) {            // Q half (zero pad)
        int row = i >> 2, c = (i & 3) << 3;
        int gr = half * 96 + row;
        uint32_t dst = (uint32_t)(row * QS + c) * 2;
        if (gr < SEQ) {
            size_t src = base + (size_t)gr * HDIM + c;
            *(uint4*)(smem + QH_B + dst) = *(const uint4*)(gQh + src);
            *(uint4*)(smem + QL_B + dst) = *(const uint4*)(gQl + src);
        } else {
            uint4 zz = make_uint4(0, 0, 0, 0);
            *(uint4*)(smem + QH_B + dst) = zz;
            *(uint4*)(smem + QL_B + dst) = zz;
        }
    }
#pragma unroll
    for (int i = tid; i < 176 * 4; i += 192) {           // V full
        int row = i >> 2, c = (i & 3) << 3;
        size_t src = base + (size_t)row * HDIM + c;
        uint32_t dst = (uint32_t)(row * QS + c) * 2;
        *(uint4*)(smem + VH_B + dst) = *(const uint4*)(gVh + src);
        *(uint4*)(smem + VL_B + dst) = *(const uint4*)(gVl + src);
    }
#pragma unroll
    for (int i = tid; i < 32 * 22; i += 192) {           // Kt full [32][176]
        int d = i / 22, t8 = (i - d * 22) << 3;
        size_t src = base + (size_t)d * SEQ + t8;
        uint32_t dst = (uint32_t)(d * KTS + t8) * 2;
        *(uint4*)(smem + KH_B + dst) = *(const uint4*)(gKth + src);
        *(uint4*)(smem + KL_B + dst) = *(const uint4*)(gKtl + src);
    }
    __syncthreads();

    const int warp = tid >> 5, lane = tid & 31;
    const int m0  = warp * 16;
    const int l16 = lane & 15, lhi = lane >> 4;
    const int qr  = lane >> 2, qc = (lane & 3) << 1;

    // ---- scores: 3-term split MMA ----
    float sc[22][4];
#pragma unroll
    for (int t = 0; t < 22; t++)
#pragma unroll
        for (int r = 0; r < 4; r++) sc[t][r] = 0.0f;

#pragma unroll
    for (int ks = 0; ks < 2; ks++) {
        uint32_t ah[4], al[4];
        uint32_t aoff = (uint32_t)((m0 + l16) * QS + ks * 16 + lhi * 8) * 2;
        LDSM_X4(ah[0], ah[1], ah[2], ah[3], sb + QH_B + aoff);
        LDSM_X4(al[0], al[1], al[2], al[3], sb + QL_B + aoff);
#pragma unroll
        for (int nt2 = 0; nt2 < 11; nt2++) {
            uint32_t boff = (uint32_t)((ks * 16 + l16) * KTS + nt2 * 16 + lhi * 8) * 2;
            uint32_t kh0, kh1, kh2, kh3, kl0, kl1, kl2, kl3;
            LDSM_X4_T(kh0, kh1, kh2, kh3, sb + KH_B + boff);
            LDSM_X4_T(kl0, kl1, kl2, kl3, sb + KL_B + boff);
            MMA_BF16_2(sc[2 * nt2],     ah, kh0, kh1);
            MMA_BF16_2(sc[2 * nt2],     ah, kl0, kl1);
            MMA_BF16_2(sc[2 * nt2],     al, kh0, kh1);
            MMA_BF16_2(sc[2 * nt2 + 1], ah, kh2, kh3);
            MMA_BF16_2(sc[2 * nt2 + 1], ah, kl2, kl3);
            MMA_BF16_2(sc[2 * nt2 + 1], al, kh2, kh3);
        }
    }

    // ---- mask + scale; invalid -> -1e30 (expf underflows to 0) ----
    const float scale = 0.17677669529663687f;
    const int sa  = half * 96 + m0 + qr;
    const int sbr = sa + 8;
    const int loa = (sa / JOINTS) * JOINTS,  hia = loa + JOINTS;
    const int lob = (sbr / JOINTS) * JOINTS, hib = lob + JOINTS;
#pragma unroll
    for (int t = 0; t < 22; t++) {
        int t0 = t * 8 + qc, t1 = t0 + 1;
        sc[t][0] = (t0 < loa || t0 >= hia || t0 == sa)  ? sc[t][0] * scale : -1e30f;
        sc[t][1] = (t1 < loa || t1 >= hia || t1 == sa)  ? sc[t][1] * scale : -1e30f;
        sc[t][2] = (t0 < lob || t0 >= hib || t0 == sbr) ? sc[t][2] * scale : -1e30f;
        sc[t][3] = (t1 < lob || t1 >= hib || t1 == sbr) ? sc[t][3] * scale : -1e30f;
    }

    // ---- streaming exp (no max) -> split att frags -> att@V ----
    float D[4][4];
#pragma unroll
    for (int nt = 0; nt < 4; nt++)
#pragma unroll
        for (int r = 0; r < 4; r++) D[nt][r] = 0.0f;
    float suma = 0.0f, sumb = 0.0f;

#pragma unroll
    for (int j = 0; j < 11; j++) {
        float e[8];
        e[0] = __expf(sc[2 * j][0]);
        e[1] = __expf(sc[2 * j][1]);
        e[2] = __expf(sc[2 * j][2]);
        e[3] = __expf(sc[2 * j][3]);
        e[4] = __expf(sc[2 * j + 1][0]);
        e[5] = __expf(sc[2 * j + 1][1]);
        e[6] = __expf(sc[2 * j + 1][2]);
        e[7] = __expf(sc[2 * j + 1][3]);
        suma += e[0] + e[1] + e[4] + e[5];
        sumb += e[2] + e[3] + e[6] + e[7];
        uint32_t af[4], alf[4];
        __nv_bfloat16 hh[8];
#pragma unroll
        for (int q = 0; q < 8; q++) hh[q] = __float2bfloat16(e[q]);
        af[0] = pk2(hh[0], hh[1]); af[1] = pk2(hh[2], hh[3]);
        af[2] = pk2(hh[4], hh[5]); af[3] = pk2(hh[6], hh[7]);
#pragma unroll
        for (int q = 0; q < 8; q++) hh[q] = __float2bfloat16(e[q] - __bfloat162float(hh[q]));
        alf[0] = pk2(hh[0], hh[1]); alf[1] = pk2(hh[2], hh[3]);
        alf[2] = pk2(hh[4], hh[5]); alf[3] = pk2(hh[6], hh[7]);
#pragma unroll
        for (int nh = 0; nh < 2; nh++) {
            uint32_t off = (uint32_t)((j * 16 + l16) * QS + nh * 16 + lhi * 8) * 2;
            uint32_t v0, v1, v2, v3, w0, w1, w2, w3;
            LDSM_X4_T(v0, v1, v2, v3, sb + VH_B + off);
            LDSM_X4_T(w0, w1, w2, w3, sb + VL_B + off);
            MMA_BF16_2(D[2 * nh],     af,  v0, v1);
            MMA_BF16_2(D[2 * nh],     af,  w0, w1);
            MMA_BF16_2(D[2 * nh],     alf, v0, v1);
            MMA_BF16_2(D[2 * nh + 1], af,  v2, v3);
            MMA_BF16_2(D[2 * nh + 1], af,  w2, w3);
            MMA_BF16_2(D[2 * nh + 1], alf, v2, v3);
        }
    }

    suma += __shfl_xor_sync(0xffffffffu, suma, 1);
    suma += __shfl_xor_sync(0xffffffffu, suma, 2);
    sumb += __shfl_xor_sync(0xffffffffu, sumb, 1);
    sumb += __shfl_xor_sync(0xffffffffu, sumb, 2);
    const float inva = 1.0f / suma, invb = 1.0f / sumb;

    float* ob = out + (size_t)b * SEQ * DMODEL + h * HDIM;
    if (sa < SEQ) {
#pragma unroll
        for (int nt = 0; nt < 4; nt++) {
            int d = nt * 8 + qc;
            float2 o; o.x = D[nt][0] * inva; o.y = D[nt][1] * inva;
            *(float2*)(ob + (size_t)sa * DMODEL + d) = o;
        }
    }
    if (sbr < SEQ) {
#pragma unroll
        for (int nt = 0; nt < 4; nt++) {
            int d = nt * 8 + qc;
            float2 o; o.x = D[nt][2] * invb; o.y = D[nt][3] * invb;
            *(float2*)(ob + (size_t)sbr * DMODEL + d) = o;
        }
    }
}

// ----------------------------------------------------------------------------
extern "C" void kernel_launch(void* const* d_in, const int* in_sizes, int n_in,
                              void* d_out, int out_size)
{
    const float* x  = (const float*)d_in[0];
    const float* Wq = (const float*)d_in[1];
    const float* bq = (const float*)d_in[2];
    const float* Wk = (const float*)d_in[3];
    const float* bk = (const float*)d_in[4];
    const float* Wv = (const float*)d_in[5];
    const float* bv = (const float*)d_in[6];
    float* out = (float*)d_out;

    cudaFuncSetAttribute(qkv_mma,
                         cudaFuncAttributeMaxDynamicSharedMemorySize, SM_QKV);
    cudaFuncSetAttribute(attn_mma,
                         cudaFuncAttributeMaxDynamicSharedMemorySize, SM_ATT);

    const int prep_blocks = (XQUADS + WQUADS + 255) / 256;
    prep_conv<<<prep_blocks, 256>>>(x, Wq, Wk, Wv);
    qkv_mma<<<dim3(MROWS / 128, DMODEL / 64, 3), 256, SM_QKV>>>(bq, bk, bv);
    attn_mma<<<BQ * HNUM * 2, 192, SM_ATT>>>(out);
}

// round 15
// speedup vs baseline: 3.3164x; 1.0910x over previous
#include <cuda_runtime.h>
#include <cuda_bf16.h>
#include <cstdint>

// ----------------------------------------------------------------------------
// MultiHeadedAttention (temporal mask).
//   B=256, S=176 (8 time x 22 joints), D_in=128, H=8, Hd=32, D_model=256
// Kernel 0: prep_conv — x,W -> bf16 hi/lo gmem images
// Kernel 1: qkv_mma   — bf16-split GEMM, z-loop in CTA (A staged once),
//                       cp.async B prefetch overlapped with epilogue
// Kernel 2: attn_mma  — FA-style tensor attention, split-wait cp.async:
//                       scores compute while V still loading
// ----------------------------------------------------------------------------

#define BQ      256
#define SEQ     176
#define DIN     128
#define DMODEL  256
#define HNUM    8
#define HDIM    32
#define MROWS   (BQ * SEQ)        // 45056
#define JOINTS  22
#define BHSZ    (SEQ * HDIM)      // 5632

// Scratch (__device__ globals; no allocation allowed)
__device__ __align__(16) __nv_bfloat16 gXhi[MROWS * DIN];
__device__ __align__(16) __nv_bfloat16 gXlo[MROWS * DIN];
__device__ __align__(16) __nv_bfloat16 gWhi3[3 * DIN * DMODEL];
__device__ __align__(16) __nv_bfloat16 gWlo3[3 * DIN * DMODEL];
// bf16 hi/lo Q,V: [bh][s][32];  K transposed: [bh][d=32][t=176]
__device__ __align__(16) __nv_bfloat16 gQh[BQ * HNUM * BHSZ];
__device__ __align__(16) __nv_bfloat16 gQl[BQ * HNUM * BHSZ];
__device__ __align__(16) __nv_bfloat16 gVh[BQ * HNUM * BHSZ];
__device__ __align__(16) __nv_bfloat16 gVl[BQ * HNUM * BHSZ];
__device__ __align__(16) __nv_bfloat16 gKth[BQ * HNUM * BHSZ];
__device__ __align__(16) __nv_bfloat16 gKtl[BQ * HNUM * BHSZ];

// ---------------- helpers ----------------
__device__ __forceinline__ uint32_t smem_u32(const void* p) {
    uint32_t a;
    asm("{ .reg .u64 t; cvta.to.shared.u64 t, %1; cvt.u32.u64 %0, t; }" : "=r"(a) : "l"(p));
    return a;
}
__device__ __forceinline__ uint32_t pk2(__nv_bfloat16 a, __nv_bfloat16 b) {
    return (uint32_t)__bfloat16_as_ushort(a) | ((uint32_t)__bfloat16_as_ushort(b) << 16);
}
__device__ __forceinline__ void split4(float4 v, uint2& hi, uint2& lo) {
    __nv_bfloat16 h0 = __float2bfloat16(v.x), h1 = __float2bfloat16(v.y);
    __nv_bfloat16 h2 = __float2bfloat16(v.z), h3 = __float2bfloat16(v.w);
    hi.x = pk2(h0, h1); hi.y = pk2(h2, h3);
    lo.x = pk2(__float2bfloat16(v.x - __bfloat162float(h0)),
               __float2bfloat16(v.y - __bfloat162float(h1)));
    lo.y = pk2(__float2bfloat16(v.z - __bfloat162float(h2)),
               __float2bfloat16(v.w - __bfloat162float(h3)));
}

#define CP_ASYNC16(saddr, gptr)                                                 \
    asm volatile("cp.async.cg.shared.global [%0], [%1], 16;"                    \
        :: "r"(saddr), "l"(gptr))
#define CP_COMMIT()  asm volatile("cp.async.commit_group;" ::: "memory")
#define CP_WAIT(n)   asm volatile("cp.async.wait_group %0;" :: "n"(n) : "memory")

#define LDSM_X4(r0, r1, r2, r3, addr)                                           \
    asm volatile("ldmatrix.sync.aligned.m8n8.x4.shared.b16 {%0,%1,%2,%3}, [%4];" \
        : "=r"(r0), "=r"(r1), "=r"(r2), "=r"(r3) : "r"(addr))
#define LDSM_X4_T(r0, r1, r2, r3, addr)                                         \
    asm volatile("ldmatrix.sync.aligned.m8n8.x4.trans.shared.b16 {%0,%1,%2,%3}, [%4];" \
        : "=r"(r0), "=r"(r1), "=r"(r2), "=r"(r3) : "r"(addr))

#define MMA_BF16(d, a, b)                                                       \
    asm volatile("mma.sync.aligned.m16n8k16.row.col.f32.bf16.bf16.f32 "         \
        "{%0,%1,%2,%3}, {%4,%5,%6,%7}, {%8,%9}, {%0,%1,%2,%3};"                 \
        : "+f"((d)[0]), "+f"((d)[1]), "+f"((d)[2]), "+f"((d)[3])                \
        : "r"((a)[0]), "r"((a)[1]), "r"((a)[2]), "r"((a)[3]),                   \
          "r"((b)[0]), "r"((b)[1]))
#define MMA_BF16_2(d, a, b0, b1)                                                \
    asm volatile("mma.sync.aligned.m16n8k16.row.col.f32.bf16.bf16.f32 "         \
        "{%0,%1,%2,%3}, {%4,%5,%6,%7}, {%8,%9}, {%0,%1,%2,%3};"                 \
        : "+f"((d)[0]), "+f"((d)[1]), "+f"((d)[2]), "+f"((d)[3])                \
        : "r"((a)[0]), "r"((a)[1]), "r"((a)[2]), "r"((a)[3]),                   \
          "r"(b0), "r"(b1))

// ----------------------------------------------------------------------------
// Kernel 0: convert x and W to bf16 hi/lo images in gmem.
// ----------------------------------------------------------------------------
#define XQUADS (MROWS * DIN / 4)
#define WQUADS (3 * DIN * DMODEL / 4)

__global__ __launch_bounds__(256) void prep_conv(
    const float* __restrict__ x,  const float* __restrict__ Wq,
    const float* __restrict__ Wk, const float* __restrict__ Wv)
{
    int idx = blockIdx.x * 256 + threadIdx.x;
    if (idx < XQUADS) {
        uint2 hi, lo;
        split4(((const float4*)x)[idx], hi, lo);
        ((uint2*)gXhi)[idx] = hi;
        ((uint2*)gXlo)[idx] = lo;
    } else {
        int w = idx - XQUADS;
        if (w < WQUADS) {
            int z = w / (DIN * DMODEL / 4);
            int r = w - z * (DIN * DMODEL / 4);
            const float* W = (z == 0) ? Wq : ((z == 1) ? Wk : Wv);
            uint2 hi, lo;
            split4(((const float4*)W)[r], hi, lo);
            ((uint2*)gWhi3)[w] = hi;
            ((uint2*)gWlo3)[w] = lo;
        }
    }
}

// ----------------------------------------------------------------------------
// Kernel 1: QKV GEMM. grid=(352,4), block=256 (8 warps: 4 wr x 2 wc),
// tile 128 rows x 64 cols, K=128, z-loop inside. 2 CTAs/SM.
// ----------------------------------------------------------------------------
#define AS 136
#define BS2 72
#define SM_AHI  0
#define SM_ALO  (SM_AHI + 128 * AS * 2)
#define SM_BHI  (SM_ALO + 128 * AS * 2)
#define SM_BLO  (SM_BHI + 128 * BS2 * 2)
#define SM_QKV  (SM_BLO + 128 * BS2 * 2)     // 106496

__global__ __launch_bounds__(256, 2) void qkv_mma(
    const float* __restrict__ bq, const float* __restrict__ bk,
    const float* __restrict__ bv)
{
    extern __shared__ char smem[];
    const uint32_t sb = smem_u32(smem);
    const int tid  = threadIdx.x;
    const int wid  = tid >> 5;
    const int lane = tid & 31;
    const int wr   = wid >> 1;
    const int wc   = wid & 1;
    const int rm   = blockIdx.x * 128;
    const int cn   = blockIdx.y * 64;

    // ---- stage A once (cp.async), plus B(z=0) ----
#pragma unroll
    for (int i = tid; i < 2048; i += 256) {
        int row = i >> 4, c = (i & 15) << 3;
        size_t src = (size_t)(rm + row) * DIN + c;
        uint32_t dst = (uint32_t)(row * AS + c) * 2;
        CP_ASYNC16(sb + SM_AHI + dst, gXhi + src);
        CP_ASYNC16(sb + SM_ALO + dst, gXlo + src);
    }
#pragma unroll
    for (int i = tid; i < 1024; i += 256) {
        int row = i >> 3, c = (i & 7) << 3;
        size_t src = (size_t)row * DMODEL + cn + c;   // z=0
        uint32_t dst = (uint32_t)(row * BS2 + c) * 2;
        CP_ASYNC16(sb + SM_BHI + dst, gWhi3 + src);
        CP_ASYNC16(sb + SM_BLO + dst, gWlo3 + src);
    }
    CP_COMMIT();

    const int l16 = lane & 15, lhi = lane >> 4;
    const int m0 = wr * 32, n0 = wc * 32;
    const int col0 = cn + wc * 32;
    const int h    = col0 >> 5;
    const int l4r  = lane >> 2;
    const int l4c  = (lane & 3) << 1;

#pragma unroll 1
    for (int z = 0; z < 3; z++) {
        CP_WAIT(0);
        __syncthreads();                   // A + B(z) resident

        float acc[2][4][4];
#pragma unroll
        for (int mt = 0; mt < 2; mt++)
#pragma unroll
            for (int nt = 0; nt < 4; nt++)
#pragma unroll
                for (int r = 0; r < 4; r++) acc[mt][nt][r] = 0.0f;

#pragma unroll
        for (int ks = 0; ks < 8; ks++) {
            uint32_t ah[2][4], al[2][4];
#pragma unroll
            for (int mt = 0; mt < 2; mt++) {
                uint32_t off = (uint32_t)((m0 + mt * 16 + l16) * AS + ks * 16 + lhi * 8) * 2;
                LDSM_X4(ah[mt][0], ah[mt][1], ah[mt][2], ah[mt][3], sb + SM_AHI + off);
                LDSM_X4(al[mt][0], al[mt][1], al[mt][2], al[mt][3], sb + SM_ALO + off);
            }
            uint32_t bh[4][2], bl[4][2];
#pragma unroll
            for (int p = 0; p < 2; p++) {
                uint32_t off = (uint32_t)((ks * 16 + l16) * BS2 + n0 + p * 16 + lhi * 8) * 2;
                uint32_t r0, r1, r2, r3;
                LDSM_X4_T(r0, r1, r2, r3, sb + SM_BHI + off);
                bh[p * 2][0] = r0; bh[p * 2][1] = r1;
                bh[p * 2 + 1][0] = r2; bh[p * 2 + 1][1] = r3;
                LDSM_X4_T(r0, r1, r2, r3, sb + SM_BLO + off);
                bl[p * 2][0] = r0; bl[p * 2][1] = r1;
                bl[p * 2 + 1][0] = r2; bl[p * 2 + 1][1] = r3;
            }
#pragma unroll
            for (int mt = 0; mt < 2; mt++)
#pragma unroll
                for (int nt = 0; nt < 4; nt++) {
                    MMA_BF16(acc[mt][nt], ah[mt], bh[nt]);
                    MMA_BF16(acc[mt][nt], ah[mt], bl[nt]);
                    MMA_BF16(acc[mt][nt], al[mt], bh[nt]);
                }
        }

        __syncthreads();                   // all warps done reading B(z)

        // prefetch B(z+1) — overlaps with the epilogue below
        if (z < 2) {
#pragma unroll
            for (int i = tid; i < 1024; i += 256) {
                int row = i >> 3, c = (i & 7) << 3;
                size_t src = ((size_t)(z + 1) * DIN + row) * DMODEL + cn + c;
                uint32_t dst = (uint32_t)(row * BS2 + c) * 2;
                CP_ASYNC16(sb + SM_BHI + dst, gWhi3 + src);
                CP_ASYNC16(sb + SM_BLO + dst, gWlo3 + src);
            }
            CP_COMMIT();
        }

        // ---- epilogue(z): bias (+ReLU for V), emit bf16 hi/lo ----
        const float* __restrict__ bias = (z == 0) ? bq : ((z == 1) ? bk : bv);
#pragma unroll
        for (int mt = 0; mt < 2; mt++) {
#pragma unroll
            for (int nt = 0; nt < 4; nt++) {
                int d = nt * 8 + l4c;
                float2 bb = *(const float2*)(bias + col0 + d);
                int g0 = rm + wr * 32 + mt * 16 + l4r;
                int b0 = g0 / SEQ, s0 = g0 - b0 * SEQ;
                int g1 = g0 + 8;
                int b1 = g1 / SEQ, s1 = g1 - b1 * SEQ;
                float ox0 = acc[mt][nt][0] + bb.x, oy0 = acc[mt][nt][1] + bb.y;
                float ox1 = acc[mt][nt][2] + bb.x, oy1 = acc[mt][nt][3] + bb.y;
                if (z == 2) {
                    ox0 = fmaxf(ox0, 0.0f); oy0 = fmaxf(oy0, 0.0f);
                    ox1 = fmaxf(ox1, 0.0f); oy1 = fmaxf(oy1, 0.0f);
                }
                __nv_bfloat16 hx0 = __float2bfloat16(ox0), hy0 = __float2bfloat16(oy0);
                __nv_bfloat16 hx1 = __float2bfloat16(ox1), hy1 = __float2bfloat16(oy1);
                __nv_bfloat16 lx0 = __float2bfloat16(ox0 - __bfloat162float(hx0));
                __nv_bfloat16 ly0 = __float2bfloat16(oy0 - __bfloat162float(hy0));
                __nv_bfloat16 lx1 = __float2bfloat16(ox1 - __bfloat162float(hx1));
                __nv_bfloat16 ly1 = __float2bfloat16(oy1 - __bfloat162float(hy1));
                if (z != 1) {
                    __nv_bfloat16* oh = (z == 0) ? gQh : gVh;
                    __nv_bfloat16* ol = (z == 0) ? gQl : gVl;
                    size_t o0 = ((size_t)(b0 * HNUM + h) * SEQ + s0) * HDIM + d;
                    size_t o1 = ((size_t)(b1 * HNUM + h) * SEQ + s1) * HDIM + d;
                    *(uint32_t*)(oh + o0) = pk2(hx0, hy0);
                    *(uint32_t*)(ol + o0) = pk2(lx0, ly0);
                    *(uint32_t*)(oh + o1) = pk2(hx1, hy1);
                    *(uint32_t*)(ol + o1) = pk2(lx1, ly1);
                } else {
                    size_t k0 = (size_t)(b0 * HNUM + h) * BHSZ + d * SEQ + s0;
                    size_t k1 = (size_t)(b1 * HNUM + h) * BHSZ + d * SEQ + s1;
                    gKth[k0] = hx0; gKth[k0 + SEQ] = hy0;
                    gKtl[k0] = lx0; gKtl[k0 + SEQ] = ly0;
                    gKth[k1] = hx1; gKth[k1 + SEQ] = hy1;
                    gKtl[k1] = lx1; gKtl[k1 + SEQ] = ly1;
                }
            }
        }
    }
}

// ----------------------------------------------------------------------------
// Kernel 2: tensor-core attention. grid=4096 (bh x 2 halves), block=192.
// Split-wait cp.async: scores run while V is still in flight.
// ----------------------------------------------------------------------------
#define QS   40
#define KTS  184
#define QH_B 0
#define QL_B (QH_B + 96 * QS * 2)
#define VH_B (QL_B + 96 * QS * 2)
#define VL_B (VH_B + 176 * QS * 2)
#define KH_B (VL_B + 176 * QS * 2)
#define KL_B (KH_B + 32 * KTS * 2)
#define SM_ATT (KL_B + 32 * KTS * 2)   // 67072 bytes

__global__ __launch_bounds__(192, 2) void attn_mma(float* __restrict__ out)
{
    extern __shared__ char smem[];
    const uint32_t sb = smem_u32(smem);
    const int bh   = blockIdx.x >> 1;
    const int half = blockIdx.x & 1;
    const int b  = bh >> 3;
    const int h  = bh & 7;
    const size_t base = (size_t)bh * BHSZ;
    const int tid = threadIdx.x;

    // ---- group 0: Q (this half) + Kt ----
#pragma unroll
    for (int i = tid; i < 96 * 4; i += 192) {
        int row = i >> 2, c = (i & 3) << 3;
        int gr = half * 96 + row;
        uint32_t dst = (uint32_t)(row * QS + c) * 2;
        if (gr < SEQ) {
            size_t src = base + (size_t)gr * HDIM + c;
            CP_ASYNC16(sb + QH_B + dst, gQh + src);
            CP_ASYNC16(sb + QL_B + dst, gQl + src);
        } else {
            uint4 zz = make_uint4(0, 0, 0, 0);
            *(uint4*)(smem + QH_B + dst) = zz;
            *(uint4*)(smem + QL_B + dst) = zz;
        }
    }
#pragma unroll
    for (int i = tid; i < 32 * 22; i += 192) {
        int d = i / 22, t8 = (i - d * 22) << 3;
        size_t src = base + (size_t)d * SEQ + t8;
        uint32_t dst = (uint32_t)(d * KTS + t8) * 2;
        CP_ASYNC16(sb + KH_B + dst, gKth + src);
        CP_ASYNC16(sb + KL_B + dst, gKtl + src);
    }
    CP_COMMIT();
    // ---- group 1: V (consumed only after scores) ----
#pragma unroll
    for (int i = tid; i < 176 * 4; i += 192) {
        int row = i >> 2, c = (i & 3) << 3;
        size_t src = base + (size_t)row * HDIM + c;
        uint32_t dst = (uint32_t)(row * QS + c) * 2;
        CP_ASYNC16(sb + VH_B + dst, gVh + src);
        CP_ASYNC16(sb + VL_B + dst, gVl + src);
    }
    CP_COMMIT();

    CP_WAIT(1);                  // Q + Kt ready; V still flying
    __syncthreads();

    const int warp = tid >> 5, lane = tid & 31;
    const int m0  = warp * 16;
    const int l16 = lane & 15, lhi = lane >> 4;
    const int qr  = lane >> 2, qc = (lane & 3) << 1;

    // ---- scores: 3-term split MMA ----
    float sc[22][4];
#pragma unroll
    for (int t = 0; t < 22; t++)
#pragma unroll
        for (int r = 0; r < 4; r++) sc[t][r] = 0.0f;

#pragma unroll
    for (int ks = 0; ks < 2; ks++) {
        uint32_t ah[4], al[4];
        uint32_t aoff = (uint32_t)((m0 + l16) * QS + ks * 16 + lhi * 8) * 2;
        LDSM_X4(ah[0], ah[1], ah[2], ah[3], sb + QH_B + aoff);
        LDSM_X4(al[0], al[1], al[2], al[3], sb + QL_B + aoff);
#pragma unroll
        for (int nt2 = 0; nt2 < 11; nt2++) {
            uint32_t boff = (uint32_t)((ks * 16 + l16) * KTS + nt2 * 16 + lhi * 8) * 2;
            uint32_t kh0, kh1, kh2, kh3, kl0, kl1, kl2, kl3;
            LDSM_X4_T(kh0, kh1, kh2, kh3, sb + KH_B + boff);
            LDSM_X4_T(kl0, kl1, kl2, kl3, sb + KL_B + boff);
            MMA_BF16_2(sc[2 * nt2],     ah, kh0, kh1);
            MMA_BF16_2(sc[2 * nt2],     ah, kl0, kl1);
            MMA_BF16_2(sc[2 * nt2],     al, kh0, kh1);
            MMA_BF16_2(sc[2 * nt2 + 1], ah, kh2, kh3);
            MMA_BF16_2(sc[2 * nt2 + 1], ah, kl2, kl3);
            MMA_BF16_2(sc[2 * nt2 + 1], al, kh2, kh3);
        }
    }

    // ---- mask + scale; invalid -> -1e30 (expf underflows to 0) ----
    const float scale = 0.17677669529663687f;
    const int sa  = half * 96 + m0 + qr;
    const int sbr = sa + 8;
    const int loa = (sa / JOINTS) * JOINTS,  hia = loa + JOINTS;
    const int lob = (sbr / JOINTS) * JOINTS, hib = lob + JOINTS;
#pragma unroll
    for (int t = 0; t < 22; t++) {
        int t0 = t * 8 + qc, t1 = t0 + 1;
        sc[t][0] = (t0 < loa || t0 >= hia || t0 == sa)  ? sc[t][0] * scale : -1e30f;
        sc[t][1] = (t1 < loa || t1 >= hia || t1 == sa)  ? sc[t][1] * scale : -1e30f;
        sc[t][2] = (t0 < lob || t0 >= hib || t0 == sbr) ? sc[t][2] * scale : -1e30f;
        sc[t][3] = (t1 < lob || t1 >= hib || t1 == sbr) ? sc[t][3] * scale : -1e30f;
    }

    CP_WAIT(0);                  // V ready
    __syncthreads();

    // ---- streaming exp (no max) -> split att frags -> att@V ----
    float D[4][4];
#pragma unroll
    for (int nt = 0; nt < 4; nt++)
#pragma unroll
        for (int r = 0; r < 4; r++) D[nt][r] = 0.0f;
    float suma = 0.0f, sumb = 0.0f;

#pragma unroll
    for (int j = 0; j < 11; j++) {
        float e[8];
        e[0] = __expf(sc[2 * j][0]);
        e[1] = __expf(sc[2 * j][1]);
        e[2] = __expf(sc[2 * j][2]);
        e[3] = __expf(sc[2 * j][3]);
        e[4] = __expf(sc[2 * j + 1][0]);
        e[5] = __expf(sc[2 * j + 1][1]);
        e[6] = __expf(sc[2 * j + 1][2]);
        e[7] = __expf(sc[2 * j + 1][3]);
        suma += e[0] + e[1] + e[4] + e[5];
        sumb += e[2] + e[3] + e[6] + e[7];
        uint32_t af[4], alf[4];
        __nv_bfloat16 hh[8];
#pragma unroll
        for (int q = 0; q < 8; q++) hh[q] = __float2bfloat16(e[q]);
        af[0] = pk2(hh[0], hh[1]); af[1] = pk2(hh[2], hh[3]);
        af[2] = pk2(hh[4], hh[5]); af[3] = pk2(hh[6], hh[7]);
#pragma unroll
        for (int q = 0; q < 8; q++) hh[q] = __float2bfloat16(e[q] - __bfloat162float(hh[q]));
        alf[0] = pk2(hh[0], hh[1]); alf[1] = pk2(hh[2], hh[3]);
        alf[2] = pk2(hh[4], hh[5]); alf[3] = pk2(hh[6], hh[7]);
#pragma unroll
        for (int nh = 0; nh < 2; nh++) {
            uint32_t off = (uint32_t)((j * 16 + l16) * QS + nh * 16 + lhi * 8) * 2;
            uint32_t v0, v1, v2, v3, w0, w1, w2, w3;
            LDSM_X4_T(v0, v1, v2, v3, sb + VH_B + off);
            LDSM_X4_T(w0, w1, w2, w3, sb + VL_B + off);
            MMA_BF16_2(D[2 * nh],     af,  v0, v1);
            MMA_BF16_2(D[2 * nh],     af,  w0, w1);
            MMA_BF16_2(D[2 * nh],     alf, v0, v1);
            MMA_BF16_2(D[2 * nh + 1], af,  v2, v3);
            MMA_BF16_2(D[2 * nh + 1], af,  w2, w3);
            MMA_BF16_2(D[2 * nh + 1], alf, v2, v3);
        }
    }

    suma += __shfl_xor_sync(0xffffffffu, suma, 1);
    suma += __shfl_xor_sync(0xffffffffu, suma, 2);
    sumb += __shfl_xor_sync(0xffffffffu, sumb, 1);
    sumb += __shfl_xor_sync(0xffffffffu, sumb, 2);
    const float inva = 1.0f / suma, invb = 1.0f / sumb;

    float* ob = out + (size_t)b * SEQ * DMODEL + h * HDIM;
    if (sa < SEQ) {
#pragma unroll
        for (int nt = 0; nt < 4; nt++) {
            int d = nt * 8 + qc;
            float2 o; o.x = D[nt][0] * inva; o.y = D[nt][1] * inva;
            *(float2*)(ob + (size_t)sa * DMODEL + d) = o;
        }
    }
    if (sbr < SEQ) {
#pragma unroll
        for (int nt = 0; nt < 4; nt++) {
            int d = nt * 8 + qc;
            float2 o; o.x = D[nt][2] * invb; o.y = D[nt][3] * invb;
            *(float2*)(ob + (size_t)sbr * DMODEL + d) = o;
        }
    }
}

// ----------------------------------------------------------------------------
extern "C" void kernel_launch(void* const* d_in, const int* in_sizes, int n_in,
                              void* d_out, int out_size)
{
    const float* x  = (const float*)d_in[0];
    const float* Wq = (const float*)d_in[1];
    const float* bq = (const float*)d_in[2];
    const float* Wk = (const float*)d_in[3];
    const float* bk = (const float*)d_in[4];
    const float* Wv = (const float*)d_in[5];
    const float* bv = (const float*)d_in[6];
    float* out = (float*)d_out;

    cudaFuncSetAttribute(qkv_mma,
                         cudaFuncAttributeMaxDynamicSharedMemorySize, SM_QKV);
    cudaFuncSetAttribute(attn_mma,
                         cudaFuncAttributeMaxDynamicSharedMemorySize, SM_ATT);

    const int prep_blocks = (XQUADS + WQUADS + 255) / 256;
    prep_conv<<<prep_blocks, 256>>>(x, Wq, Wk, Wv);
    qkv_mma<<<dim3(MROWS / 128, DMODEL / 64), 256, SM_QKV>>>(bq, bk, bv);
    attn_mma<<<BQ * HNUM * 2, 192, SM_ATT>>>(out);
}

// round 16
// speedup vs baseline: 4.4786x; 1.3505x over previous
#include <cuda_runtime.h>
#include <cuda_bf16.h>
#include <cuda_fp16.h>
#include <cstdint>

// ----------------------------------------------------------------------------
// MultiHeadedAttention (temporal mask).
//   B=256, S=176 (8 time x 22 joints), D_in=128, H=8, Hd=32, D_model=256
// Kernel 0: prep_conv — x,W -> bf16 hi/lo gmem images (for qkv precision)
// Kernel 1: qkv_mma   — bf16-split GEMM (3 terms, ~1e-5 exact); epilogue emits
//                       SINGLE fp16 Q,V and pre-transposed K
// Kernel 2: attn_mma  — fp16 single-term tensor attention (err ~3e-4):
//                       1 MMA/tile for scores and AV, half smem/staging
// ----------------------------------------------------------------------------

#define BQ      256
#define SEQ     176
#define DIN     128
#define DMODEL  256
#define HNUM    8
#define HDIM    32
#define MROWS   (BQ * SEQ)        // 45056
#define JOINTS  22
#define BHSZ    (SEQ * HDIM)      // 5632

// Scratch (__device__ globals; no allocation allowed)
__device__ __align__(16) __nv_bfloat16 gXhi[MROWS * DIN];
__device__ __align__(16) __nv_bfloat16 gXlo[MROWS * DIN];
__device__ __align__(16) __nv_bfloat16 gWhi3[3 * DIN * DMODEL];
__device__ __align__(16) __nv_bfloat16 gWlo3[3 * DIN * DMODEL];
// fp16 Q,V: [bh][s][32];  K transposed: [bh][d=32][t=176]
__device__ __align__(16) __half gQ16[BQ * HNUM * BHSZ];
__device__ __align__(16) __half gV16[BQ * HNUM * BHSZ];
__device__ __align__(16) __half gKt16[BQ * HNUM * BHSZ];

// ---------------- helpers ----------------
__device__ __forceinline__ uint32_t smem_u32(const void* p) {
    uint32_t a;
    asm("{ .reg .u64 t; cvta.to.shared.u64 t, %1; cvt.u32.u64 %0, t; }" : "=r"(a) : "l"(p));
    return a;
}
__device__ __forceinline__ uint32_t pk2(__nv_bfloat16 a, __nv_bfloat16 b) {
    return (uint32_t)__bfloat16_as_ushort(a) | ((uint32_t)__bfloat16_as_ushort(b) << 16);
}
__device__ __forceinline__ uint32_t pk2h(float a, float b) {
    __half2 h = __floats2half2_rn(a, b);
    return *(uint32_t*)&h;
}
__device__ __forceinline__ void split4(float4 v, uint2& hi, uint2& lo) {
    __nv_bfloat16 h0 = __float2bfloat16(v.x), h1 = __float2bfloat16(v.y);
    __nv_bfloat16 h2 = __float2bfloat16(v.z), h3 = __float2bfloat16(v.w);
    hi.x = pk2(h0, h1); hi.y = pk2(h2, h3);
    lo.x = pk2(__float2bfloat16(v.x - __bfloat162float(h0)),
               __float2bfloat16(v.y - __bfloat162float(h1)));
    lo.y = pk2(__float2bfloat16(v.z - __bfloat162float(h2)),
               __float2bfloat16(v.w - __bfloat162float(h3)));
}

#define CP_ASYNC16(saddr, gptr)                                                 \
    asm volatile("cp.async.cg.shared.global [%0], [%1], 16;"                    \
        :: "r"(saddr), "l"(gptr))
#define CP_COMMIT()  asm volatile("cp.async.commit_group;" ::: "memory")
#define CP_WAIT(n)   asm volatile("cp.async.wait_group %0;" :: "n"(n) : "memory")

#define LDSM_X4(r0, r1, r2, r3, addr)                                           \
    asm volatile("ldmatrix.sync.aligned.m8n8.x4.shared.b16 {%0,%1,%2,%3}, [%4];" \
        : "=r"(r0), "=r"(r1), "=r"(r2), "=r"(r3) : "r"(addr))
#define LDSM_X4_T(r0, r1, r2, r3, addr)                                         \
    asm volatile("ldmatrix.sync.aligned.m8n8.x4.trans.shared.b16 {%0,%1,%2,%3}, [%4];" \
        : "=r"(r0), "=r"(r1), "=r"(r2), "=r"(r3) : "r"(addr))

#define MMA_BF16(d, a, b)                                                       \
    asm volatile("mma.sync.aligned.m16n8k16.row.col.f32.bf16.bf16.f32 "         \
        "{%0,%1,%2,%3}, {%4,%5,%6,%7}, {%8,%9}, {%0,%1,%2,%3};"                 \
        : "+f"((d)[0]), "+f"((d)[1]), "+f"((d)[2]), "+f"((d)[3])                \
        : "r"((a)[0]), "r"((a)[1]), "r"((a)[2]), "r"((a)[3]),                   \
          "r"((b)[0]), "r"((b)[1]))
#define MMA_F16_2(d, a, b0, b1)                                                 \
    asm volatile("mma.sync.aligned.m16n8k16.row.col.f32.f16.f16.f32 "           \
        "{%0,%1,%2,%3}, {%4,%5,%6,%7}, {%8,%9}, {%0,%1,%2,%3};"                 \
        : "+f"((d)[0]), "+f"((d)[1]), "+f"((d)[2]), "+f"((d)[3])                \
        : "r"((a)[0]), "r"((a)[1]), "r"((a)[2]), "r"((a)[3]),                   \
          "r"(b0), "r"(b1))

// ----------------------------------------------------------------------------
// Kernel 0: convert x and W to bf16 hi/lo images in gmem.
// ----------------------------------------------------------------------------
#define XQUADS (MROWS * DIN / 4)
#define WQUADS (3 * DIN * DMODEL / 4)

__global__ __launch_bounds__(256) void prep_conv(
    const float* __restrict__ x,  const float* __restrict__ Wq,
    const float* __restrict__ Wk, const float* __restrict__ Wv)
{
    int idx = blockIdx.x * 256 + threadIdx.x;
    if (idx < XQUADS) {
        uint2 hi, lo;
        split4(((const float4*)x)[idx], hi, lo);
        ((uint2*)gXhi)[idx] = hi;
        ((uint2*)gXlo)[idx] = lo;
    } else {
        int w = idx - XQUADS;
        if (w < WQUADS) {
            int z = w / (DIN * DMODEL / 4);
            int r = w - z * (DIN * DMODEL / 4);
            const float* W = (z == 0) ? Wq : ((z == 1) ? Wk : Wv);
            uint2 hi, lo;
            split4(((const float4*)W)[r], hi, lo);
            ((uint2*)gWhi3)[w] = hi;
            ((uint2*)gWlo3)[w] = lo;
        }
    }
}

// ----------------------------------------------------------------------------
// Kernel 1: QKV GEMM. grid=(352,4), block=256 (8 warps: 4 wr x 2 wc),
// tile 128 rows x 64 cols, K=128, z-loop inside. 2 CTAs/SM.
// ----------------------------------------------------------------------------
#define AS 136
#define BS2 72
#define SM_AHI  0
#define SM_ALO  (SM_AHI + 128 * AS * 2)
#define SM_BHI  (SM_ALO + 128 * AS * 2)
#define SM_BLO  (SM_BHI + 128 * BS2 * 2)
#define SM_QKV  (SM_BLO + 128 * BS2 * 2)     // 106496

__global__ __launch_bounds__(256, 2) void qkv_mma(
    const float* __restrict__ bq, const float* __restrict__ bk,
    const float* __restrict__ bv)
{
    extern __shared__ char smem[];
    const uint32_t sb = smem_u32(smem);
    const int tid  = threadIdx.x;
    const int wid  = tid >> 5;
    const int lane = tid & 31;
    const int wr   = wid >> 1;
    const int wc   = wid & 1;
    const int rm   = blockIdx.x * 128;
    const int cn   = blockIdx.y * 64;

    // ---- stage A once (cp.async), plus B(z=0) ----
#pragma unroll
    for (int i = tid; i < 2048; i += 256) {
        int row = i >> 4, c = (i & 15) << 3;
        size_t src = (size_t)(rm + row) * DIN + c;
        uint32_t dst = (uint32_t)(row * AS + c) * 2;
        CP_ASYNC16(sb + SM_AHI + dst, gXhi + src);
        CP_ASYNC16(sb + SM_ALO + dst, gXlo + src);
    }
#pragma unroll
    for (int i = tid; i < 1024; i += 256) {
        int row = i >> 3, c = (i & 7) << 3;
        size_t src = (size_t)row * DMODEL + cn + c;   // z=0
        uint32_t dst = (uint32_t)(row * BS2 + c) * 2;
        CP_ASYNC16(sb + SM_BHI + dst, gWhi3 + src);
        CP_ASYNC16(sb + SM_BLO + dst, gWlo3 + src);
    }
    CP_COMMIT();

    const int l16 = lane & 15, lhi = lane >> 4;
    const int m0 = wr * 32, n0 = wc * 32;
    const int col0 = cn + wc * 32;
    const int h    = col0 >> 5;
    const int l4r  = lane >> 2;
    const int l4c  = (lane & 3) << 1;

#pragma unroll 1
    for (int z = 0; z < 3; z++) {
        CP_WAIT(0);
        __syncthreads();                   // A + B(z) resident

        float acc[2][4][4];
#pragma unroll
        for (int mt = 0; mt < 2; mt++)
#pragma unroll
            for (int nt = 0; nt < 4; nt++)
#pragma unroll
                for (int r = 0; r < 4; r++) acc[mt][nt][r] = 0.0f;

#pragma unroll
        for (int ks = 0; ks < 8; ks++) {
            uint32_t ah[2][4], al[2][4];
#pragma unroll
            for (int mt = 0; mt < 2; mt++) {
                uint32_t off = (uint32_t)((m0 + mt * 16 + l16) * AS + ks * 16 + lhi * 8) * 2;
                LDSM_X4(ah[mt][0], ah[mt][1], ah[mt][2], ah[mt][3], sb + SM_AHI + off);
                LDSM_X4(al[mt][0], al[mt][1], al[mt][2], al[mt][3], sb + SM_ALO + off);
            }
            uint32_t bh[4][2], bl[4][2];
#pragma unroll
            for (int p = 0; p < 2; p++) {
                uint32_t off = (uint32_t)((ks * 16 + l16) * BS2 + n0 + p * 16 + lhi * 8) * 2;
                uint32_t r0, r1, r2, r3;
                LDSM_X4_T(r0, r1, r2, r3, sb + SM_BHI + off);
                bh[p * 2][0] = r0; bh[p * 2][1] = r1;
                bh[p * 2 + 1][0] = r2; bh[p * 2 + 1][1] = r3;
                LDSM_X4_T(r0, r1, r2, r3, sb + SM_BLO + off);
                bl[p * 2][0] = r0; bl[p * 2][1] = r1;
                bl[p * 2 + 1][0] = r2; bl[p * 2 + 1][1] = r3;
            }
#pragma unroll
            for (int mt = 0; mt < 2; mt++)
#pragma unroll
                for (int nt = 0; nt < 4; nt++) {
                    MMA_BF16(acc[mt][nt], ah[mt], bh[nt]);
                    MMA_BF16(acc[mt][nt], ah[mt], bl[nt]);
                    MMA_BF16(acc[mt][nt], al[mt], bh[nt]);
                }
        }

        __syncthreads();                   // all warps done reading B(z)

        // prefetch B(z+1) — overlaps with the epilogue below
        if (z < 2) {
#pragma unroll
            for (int i = tid; i < 1024; i += 256) {
                int row = i >> 3, c = (i & 7) << 3;
                size_t src = ((size_t)(z + 1) * DIN + row) * DMODEL + cn + c;
                uint32_t dst = (uint32_t)(row * BS2 + c) * 2;
                CP_ASYNC16(sb + SM_BHI + dst, gWhi3 + src);
                CP_ASYNC16(sb + SM_BLO + dst, gWlo3 + src);
            }
            CP_COMMIT();
        }

        // ---- epilogue(z): bias (+ReLU for V), emit fp16 ----
        const float* __restrict__ bias = (z == 0) ? bq : ((z == 1) ? bk : bv);
#pragma unroll
        for (int mt = 0; mt < 2; mt++) {
#pragma unroll
            for (int nt = 0; nt < 4; nt++) {
                int d = nt * 8 + l4c;
                float2 bb = *(const float2*)(bias + col0 + d);
                int g0 = rm + wr * 32 + mt * 16 + l4r;
                int b0 = g0 / SEQ, s0 = g0 - b0 * SEQ;
                int g1 = g0 + 8;
                int b1 = g1 / SEQ, s1 = g1 - b1 * SEQ;
                float ox0 = acc[mt][nt][0] + bb.x, oy0 = acc[mt][nt][1] + bb.y;
                float ox1 = acc[mt][nt][2] + bb.x, oy1 = acc[mt][nt][3] + bb.y;
                if (z == 2) {
                    ox0 = fmaxf(ox0, 0.0f); oy0 = fmaxf(oy0, 0.0f);
                    ox1 = fmaxf(ox1, 0.0f); oy1 = fmaxf(oy1, 0.0f);
                }
                if (z != 1) {
                    __half* oh = (z == 0) ? gQ16 : gV16;
                    size_t o0 = ((size_t)(b0 * HNUM + h) * SEQ + s0) * HDIM + d;
                    size_t o1 = ((size_t)(b1 * HNUM + h) * SEQ + s1) * HDIM + d;
                    *(uint32_t*)(oh + o0) = pk2h(ox0, oy0);
                    *(uint32_t*)(oh + o1) = pk2h(ox1, oy1);
                } else {
                    size_t k0 = (size_t)(b0 * HNUM + h) * BHSZ + d * SEQ + s0;
                    size_t k1 = (size_t)(b1 * HNUM + h) * BHSZ + d * SEQ + s1;
                    gKt16[k0] = __float2half_rn(ox0);
                    gKt16[k0 + SEQ] = __float2half_rn(oy0);
                    gKt16[k1] = __float2half_rn(ox1);
                    gKt16[k1 + SEQ] = __float2half_rn(oy1);
                }
            }
        }
    }
}

// ----------------------------------------------------------------------------
// Kernel 2: fp16 tensor attention. grid=4096 (bh x 2 halves), block=192.
// Single-term MMAs; split-wait cp.async (scores run while V in flight).
// ----------------------------------------------------------------------------
#define QS   40
#define KTS  184
#define QH_B 0
#define VH_B (QH_B + 96 * QS * 2)      // 7680
#define KH_B (VH_B + 176 * QS * 2)     // 21760
#define SM_ATT (KH_B + 32 * KTS * 2)   // 33536 bytes

__global__ __launch_bounds__(192, 2) void attn_mma(float* __restrict__ out)
{
    extern __shared__ char smem[];
    const uint32_t sb = smem_u32(smem);
    const int bh   = blockIdx.x >> 1;
    const int half = blockIdx.x & 1;
    const int b  = bh >> 3;
    const int h  = bh & 7;
    const size_t base = (size_t)bh * BHSZ;
    const int tid = threadIdx.x;

    // ---- group 0: Q (this half) + Kt ----
#pragma unroll
    for (int i = tid; i < 96 * 4; i += 192) {
        int row = i >> 2, c = (i & 3) << 3;
        int gr = half * 96 + row;
        uint32_t dst = (uint32_t)(row * QS + c) * 2;
        if (gr < SEQ) {
            CP_ASYNC16(sb + QH_B + dst, gQ16 + base + (size_t)gr * HDIM + c);
        } else {
            *(uint4*)(smem + QH_B + dst) = make_uint4(0, 0, 0, 0);
        }
    }
#pragma unroll
    for (int i = tid; i < 32 * 22; i += 192) {
        int d = i / 22, t8 = (i - d * 22) << 3;
        uint32_t dst = (uint32_t)(d * KTS + t8) * 2;
        CP_ASYNC16(sb + KH_B + dst, gKt16 + base + (size_t)d * SEQ + t8);
    }
    CP_COMMIT();
    // ---- group 1: V ----
#pragma unroll
    for (int i = tid; i < 176 * 4; i += 192) {
        int row = i >> 2, c = (i & 3) << 3;
        uint32_t dst = (uint32_t)(row * QS + c) * 2;
        CP_ASYNC16(sb + VH_B + dst, gV16 + base + (size_t)row * HDIM + c);
    }
    CP_COMMIT();

    CP_WAIT(1);                  // Q + Kt ready; V still flying
    __syncthreads();

    const int warp = tid >> 5, lane = tid & 31;
    const int m0  = warp * 16;
    const int l16 = lane & 15, lhi = lane >> 4;
    const int qr  = lane >> 2, qc = (lane & 3) << 1;

    // ---- scores: single fp16 MMA per tile ----
    float sc[22][4];
#pragma unroll
    for (int t = 0; t < 22; t++)
#pragma unroll
        for (int r = 0; r < 4; r++) sc[t][r] = 0.0f;

#pragma unroll
    for (int ks = 0; ks < 2; ks++) {
        uint32_t ah[4];
        uint32_t aoff = (uint32_t)((m0 + l16) * QS + ks * 16 + lhi * 8) * 2;
        LDSM_X4(ah[0], ah[1], ah[2], ah[3], sb + QH_B + aoff);
#pragma unroll
        for (int nt2 = 0; nt2 < 11; nt2++) {
            uint32_t boff = (uint32_t)((ks * 16 + l16) * KTS + nt2 * 16 + lhi * 8) * 2;
            uint32_t kh0, kh1, kh2, kh3;
            LDSM_X4_T(kh0, kh1, kh2, kh3, sb + KH_B + boff);
            MMA_F16_2(sc[2 * nt2],     ah, kh0, kh1);
            MMA_F16_2(sc[2 * nt2 + 1], ah, kh2, kh3);
        }
    }

    // ---- mask + scale; invalid -> -1e30 (expf underflows to 0) ----
    const float scale = 0.17677669529663687f;
    const int sa  = half * 96 + m0 + qr;
    const int sbr = sa + 8;
    const int loa = (sa / JOINTS) * JOINTS,  hia = loa + JOINTS;
    const int lob = (sbr / JOINTS) * JOINTS, hib = lob + JOINTS;
#pragma unroll
    for (int t = 0; t < 22; t++) {
        int t0 = t * 8 + qc, t1 = t0 + 1;
        sc[t][0] = (t0 < loa || t0 >= hia || t0 == sa)  ? sc[t][0] * scale : -1e30f;
        sc[t][1] = (t1 < loa || t1 >= hia || t1 == sa)  ? sc[t][1] * scale : -1e30f;
        sc[t][2] = (t0 < lob || t0 >= hib || t0 == sbr) ? sc[t][2] * scale : -1e30f;
        sc[t][3] = (t1 < lob || t1 >= hib || t1 == sbr) ? sc[t][3] * scale : -1e30f;
    }

    CP_WAIT(0);                  // V ready
    __syncthreads();

    // ---- streaming exp -> fp16 att frags -> att@V (single term) ----
    float D[4][4];
#pragma unroll
    for (int nt = 0; nt < 4; nt++)
#pragma unroll
        for (int r = 0; r < 4; r++) D[nt][r] = 0.0f;
    float suma = 0.0f, sumb = 0.0f;

#pragma unroll
    for (int j = 0; j < 11; j++) {
        float e[8];
        e[0] = __expf(sc[2 * j][0]);
        e[1] = __expf(sc[2 * j][1]);
        e[2] = __expf(sc[2 * j][2]);
        e[3] = __expf(sc[2 * j][3]);
        e[4] = __expf(sc[2 * j + 1][0]);
        e[5] = __expf(sc[2 * j + 1][1]);
        e[6] = __expf(sc[2 * j + 1][2]);
        e[7] = __expf(sc[2 * j + 1][3]);
        suma += e[0] + e[1] + e[4] + e[5];
        sumb += e[2] + e[3] + e[6] + e[7];
        uint32_t af[4];
        af[0] = pk2h(e[0], e[1]); af[1] = pk2h(e[2], e[3]);
        af[2] = pk2h(e[4], e[5]); af[3] = pk2h(e[6], e[7]);
#pragma unroll
        for (int nh = 0; nh < 2; nh++) {
            uint32_t off = (uint32_t)((j * 16 + l16) * QS + nh * 16 + lhi * 8) * 2;
            uint32_t v0, v1, v2, v3;
            LDSM_X4_T(v0, v1, v2, v3, sb + VH_B + off);
            MMA_F16_2(D[2 * nh],     af, v0, v1);
            MMA_F16_2(D[2 * nh + 1], af, v2, v3);
        }
    }

    suma += __shfl_xor_sync(0xffffffffu, suma, 1);
    suma += __shfl_xor_sync(0xffffffffu, suma, 2);
    sumb += __shfl_xor_sync(0xffffffffu, sumb, 1);
    sumb += __shfl_xor_sync(0xffffffffu, sumb, 2);
    const float inva = 1.0f / suma, invb = 1.0f / sumb;

    float* ob = out + (size_t)b * SEQ * DMODEL + h * HDIM;
    if (sa < SEQ) {
#pragma unroll
        for (int nt = 0; nt < 4; nt++) {
            int d = nt * 8 + qc;
            float2 o; o.x = D[nt][0] * inva; o.y = D[nt][1] * inva;
            *(float2*)(ob + (size_t)sa * DMODEL + d) = o;
        }
    }
    if (sbr < SEQ) {
#pragma unroll
        for (int nt = 0; nt < 4; nt++) {
            int d = nt * 8 + qc;
            float2 o; o.x = D[nt][2] * invb; o.y = D[nt][3] * invb;
            *(float2*)(ob + (size_t)sbr * DMODEL + d) = o;
        }
    }
}

// ----------------------------------------------------------------------------
extern "C" void kernel_launch(void* const* d_in, const int* in_sizes, int n_in,
                              void* d_out, int out_size)
{
    const float* x  = (const float*)d_in[0];
    const float* Wq = (const float*)d_in[1];
    const float* bq = (const float*)d_in[2];
    const float* Wk = (const float*)d_in[3];
    const float* bk = (const float*)d_in[4];
    const float* Wv = (const float*)d_in[5];
    const float* bv = (const float*)d_in[6];
    float* out = (float*)d_out;

    cudaFuncSetAttribute(qkv_mma,
                         cudaFuncAttributeMaxDynamicSharedMemorySize, SM_QKV);
    cudaFuncSetAttribute(attn_mma,
                         cudaFuncAttributeMaxDynamicSharedMemorySize, SM_ATT);

    const int prep_blocks = (XQUADS + WQUADS + 255) / 256;
    prep_conv<<<prep_blocks, 256>>>(x, Wq, Wk, Wv);
    qkv_mma<<<dim3(MROWS / 128, DMODEL / 64), 256, SM_QKV>>>(bq, bk, bv);
    attn_mma<<<BQ * HNUM * 2, 192, SM_ATT>>>(out);
}